// round 10
// baseline (speedup 1.0000x reference)
#include <cuda_runtime.h>
#include <cuda_bf16.h>
#include <math.h>
#include <stdint.h>

#define T_ 2048
#define C_ 2048
#define H_ 32
#define S_ 64
#define HKV_ 8
#define LMAA_ 32
#define LDEC_ 64
#define K3_ (3 * C_)   // 6144
#define SPLITK 4

// ---------------- f32 scratch ----------------
__device__ float g_sx [T_*C_];
__device__ float g_t1 [T_*5*LMAA_];
__device__ float g_t2 [T_*LDEC_];
__device__ float g_r  [T_*C_];
__device__ float g_k  [T_*HKV_*S_];
__device__ float g_v  [T_*HKV_*S_];
__device__ float g_ew [T_*C_];
__device__ float g_gate[T_*C_];
__device__ float g_sfin[H_*S_*S_];
__device__ float g_part[SPLITK * T_ * (5*LMAA_ + LDEC_)];

// ---------------- bf16 3-split buffers (A'=[hi|hi|lo], W'=[hi|lo|hi]) ----------------
__device__ __align__(128) __nv_bfloat16 g_ba_xxx[(size_t)T_ * K3_];
__device__ __align__(128) __nv_bfloat16 g_ba_r  [(size_t)T_ * K3_];   // xr, later reused for out
__device__ __align__(128) __nv_bfloat16 g_ba_k  [(size_t)T_ * K3_];
__device__ __align__(128) __nv_bfloat16 g_ba_v  [(size_t)T_ * K3_];
__device__ __align__(128) __nv_bfloat16 g_ba_w  [(size_t)T_ * K3_];
__device__ __align__(128) __nv_bfloat16 g_ba_g  [(size_t)T_ * K3_];
__device__ __align__(128) __nv_bfloat16 g_bwA[(size_t)2048 * K3_];    // Wq, later Wo
__device__ __align__(128) __nv_bfloat16 g_bwB[(size_t)2048 * K3_];    // Wg
__device__ __align__(128) __nv_bfloat16 g_bw1[(size_t)512 * K3_];     // Wk
__device__ __align__(128) __nv_bfloat16 g_bw2[(size_t)512 * K3_];     // Wv
__device__ __align__(128) __nv_bfloat16 g_bws1[(size_t)256 * K3_];    // maa_w1 (160->256)
__device__ __align__(128) __nv_bfloat16 g_bws2[(size_t)256 * K3_];    // dec_w1 (64->256)

// ---------------- epilogue ids ----------------
#define EPI_NONE  0
#define EPI_TANH  1
#define EPI_SIG   2
#define EPI_MIX   3
#define EPI_DECAY 4

// ---------------- mma.sync helpers ----------------
__device__ __forceinline__ uint32_t smem_u32(const void* p) {
    uint32_t a;
    asm("{ .reg .u64 t; cvta.to.shared.u64 t, %1; cvt.u32.u64 %0, t; }" : "=r"(a) : "l"(p));
    return a;
}
__device__ __forceinline__ void cp_async16(uint32_t saddr, const void* g) {
    asm volatile("cp.async.cg.shared.global [%0], [%1], 16;" :: "r"(saddr), "l"(g) : "memory");
}
__device__ __forceinline__ void ldmatrix_x4(uint32_t* r, uint32_t addr) {
    asm volatile("ldmatrix.sync.aligned.m8n8.x4.shared.b16 {%0,%1,%2,%3}, [%4];"
        : "=r"(r[0]), "=r"(r[1]), "=r"(r[2]), "=r"(r[3]) : "r"(addr));
}
__device__ __forceinline__ void mma16816(float* c, const uint32_t* a, uint32_t b0, uint32_t b1) {
    asm volatile("mma.sync.aligned.m16n8k16.row.col.f32.bf16.bf16.f32 "
        "{%0,%1,%2,%3}, {%4,%5,%6,%7}, {%8,%9}, {%0,%1,%2,%3};"
        : "+f"(c[0]), "+f"(c[1]), "+f"(c[2]), "+f"(c[3])
        : "r"(a[0]), "r"(a[1]), "r"(a[2]), "r"(a[3]), "r"(b0), "r"(b1));
}

struct TB {
    const __nv_bfloat16* A[4];
    const __nv_bfloat16* B[4];
    float*               Cc[4];
    int N[4];
    int ldc[4];
    int epi[4];
};

// ---------------- HMMA bf16 GEMM v2: C = A'[M,K'] @ B'[N,K']^T ----------------
// CTA tile 128x256, 8 warps (2m x 4n), warp tile 64x64 (128 accum regs/thread).
// BK=64, 3-stage cp.async pipeline (48KB/stage), SW128-xor swizzled smem.
// splitStride>0: split-K mode (z = split idx, entry 0, kc0 = z*nch, C += z*splitStride).
__global__ __launch_bounds__(256, 1)
void hgemm(TB bt, int nch, int splitStride)
{
    const int z = blockIdx.z;
    const __nv_bfloat16* __restrict__ Ag;
    const __nv_bfloat16* __restrict__ Bg;
    float* __restrict__ Cg;
    int N, ldc, epi, kc0 = 0;
    if (splitStride > 0) {
        Ag = bt.A[0]; Bg = bt.B[0]; N = bt.N[0]; ldc = bt.ldc[0]; epi = bt.epi[0];
        Cg = bt.Cc[0] + (size_t)z * splitStride;
        kc0 = z * nch;
    } else {
        Ag = bt.A[z]; Bg = bt.B[z]; Cg = bt.Cc[z];
        N = bt.N[z]; ldc = bt.ldc[z]; epi = bt.epi[z];
    }
    if (blockIdx.x * 256 >= N) return;

    extern __shared__ char smem[];
    const uint32_t sbase = smem_u32(smem);   // 3 stages x (A 16KB | B 32KB)

    const int tid  = threadIdx.x;
    const int lane = tid & 31;
    const int wid  = tid >> 5;
    const int wm   = wid >> 2;    // 0..1
    const int wn   = wid & 3;     // 0..3
    const int bx = blockIdx.x, by = blockIdx.y;

    float acc[4][8][4];
    #pragma unroll
    for (int i = 0; i < 4; i++)
        #pragma unroll
        for (int j = 0; j < 8; j++)
            #pragma unroll
            for (int k = 0; k < 4; k++) acc[i][j][k] = 0.f;

    const __nv_bfloat16* Abase = Ag + (size_t)(by * 128) * K3_;
    const __nv_bfloat16* Bbase = Bg + (size_t)(bx * 256) * K3_;

    // stage: A 128 rows x 128B (16KB), B 256 rows x 128B (32KB)
    auto load_stage = [&](int kt, int s) {
        const uint32_t sa = sbase + s * 49152;
        const uint32_t sb = sa + 16384;
        const __nv_bfloat16* Agk = Abase + (size_t)(kc0 + kt) * 64;
        const __nv_bfloat16* Bgk = Bbase + (size_t)(kc0 + kt) * 64;
        #pragma unroll
        for (int q = 0; q < 4; q++) {
            const int c = q * 256 + tid;
            const int row = c >> 3, j = c & 7;
            uint32_t off = (uint32_t)(row * 128 + j * 16);
            off ^= (off >> 3) & 0x70;
            cp_async16(sa + off, Agk + (size_t)row * K3_ + j * 8);
        }
        #pragma unroll
        for (int q = 0; q < 8; q++) {
            const int c = q * 256 + tid;
            const int row = c >> 3, j = c & 7;
            uint32_t off = (uint32_t)(row * 128 + j * 16);
            off ^= (off >> 3) & 0x70;
            cp_async16(sb + off, Bgk + (size_t)row * K3_ + j * 8);
        }
        asm volatile("cp.async.commit_group;" ::: "memory");
    };

    const int a_roff = (wm * 64 + (lane & 15)) * 128 + (lane >> 4) * 16;
    const int b_roff = (wn * 64 + (lane & 7) + ((lane >> 4) << 3)) * 128 + ((lane >> 3) & 1) * 16;

    auto compute = [&](int s) {
        const uint32_t sa = sbase + s * 49152;
        const uint32_t sbb = sa + 16384;
        #pragma unroll
        for (int ks = 0; ks < 4; ks++) {
            uint32_t bf2[4][4];
            #pragma unroll
            for (int nt2 = 0; nt2 < 4; nt2++) {
                uint32_t off = (uint32_t)(b_roff + nt2 * 16 * 128 + ks * 32);
                off ^= (off >> 3) & 0x70;
                ldmatrix_x4(bf2[nt2], sbb + off);
            }
            uint32_t af[4][4];
            #pragma unroll
            for (int mt = 0; mt < 4; mt++) {
                uint32_t off = (uint32_t)(a_roff + mt * 16 * 128 + ks * 32);
                off ^= (off >> 3) & 0x70;
                ldmatrix_x4(af[mt], sa + off);
            }
            #pragma unroll
            for (int mt = 0; mt < 4; mt++)
                #pragma unroll
                for (int nt = 0; nt < 8; nt++)
                    mma16816(acc[mt][nt], af[mt],
                             bf2[nt >> 1][(nt & 1) * 2], bf2[nt >> 1][(nt & 1) * 2 + 1]);
        }
    };

    load_stage(0, 0);
    load_stage(1, 1);

    for (int kt = 0; kt < nch; kt++) {
        asm volatile("cp.async.wait_group 1;" ::: "memory");
        __syncthreads();
        if (kt + 2 < nch) load_stage(kt + 2, (kt + 2) % 3);
        else asm volatile("cp.async.commit_group;" ::: "memory");
        compute(kt % 3);
    }

    // epilogue (runtime epi: NONE / TANH / SIG)
    #pragma unroll
    for (int mt = 0; mt < 4; mt++) {
        #pragma unroll
        for (int hrow = 0; hrow < 2; hrow++) {
            const int row = by * 128 + wm * 64 + mt * 16 + hrow * 8 + (lane >> 2);
            float* crow = Cg + (size_t)row * ldc;
            #pragma unroll
            for (int nt = 0; nt < 8; nt++) {
                const int col = bx * 256 + wn * 64 + nt * 8 + (lane & 3) * 2;
                if (col >= N) continue;
                float v0 = acc[mt][nt][hrow * 2 + 0];
                float v1 = acc[mt][nt][hrow * 2 + 1];
                if (epi == EPI_TANH) { v0 = tanhf(v0); v1 = tanhf(v1); }
                else if (epi == EPI_SIG) { v0 = 1.f/(1.f+expf(-v0)); v1 = 1.f/(1.f+expf(-v1)); }
                *(float2*)&crow[col] = make_float2(v0, v1);
            }
        }
    }
}

// ---------------- split-K reducer + tanh ----------------
__global__ void k_red_tanh(const float* __restrict__ part, float* __restrict__ out,
                           int n, int stride)
{
    int i = blockIdx.x * blockDim.x + threadIdx.x;
    if (i >= n) return;
    float s = part[i] + part[(size_t)stride + i]
            + part[(size_t)2 * stride + i] + part[(size_t)3 * stride + i];
    out[i] = tanhf(s);
}

// weights: src[2048 x N] f32 -> dst[Npad x 6144] bf16 as rows n: [hi | lo | hi], transposed
__global__ void k_conv_w(const float* __restrict__ src, __nv_bfloat16* __restrict__ dst, int N)
{
    __shared__ float tile[32][33];
    const int n0 = blockIdx.x * 32;
    const int k0 = blockIdx.y * 32;
    const int tx = threadIdx.x, ty = threadIdx.y;  // (32, 8)
    #pragma unroll
    for (int yy = 0; yy < 32; yy += 8) {
        int n = n0 + tx, k = k0 + ty + yy;
        tile[ty + yy][tx] = (n < N) ? src[(size_t)k * N + n] : 0.f;
    }
    __syncthreads();
    #pragma unroll
    for (int yy = 0; yy < 32; yy += 8) {
        int n = n0 + ty + yy;
        int k = k0 + tx;
        float a = tile[tx][ty + yy];
        __nv_bfloat16 hi = __float2bfloat16(a);
        __nv_bfloat16 lo = __float2bfloat16(a - __bfloat162float(hi));
        size_t base = (size_t)n * K3_;
        dst[base + k] = hi;
        dst[base + C_ + k] = lo;
        dst[base + 2 * C_ + k] = hi;
    }
}

// ---------------- FFMA2 GEMM (small-K: MIX K=32 -> bf16 split out, DECAY K=64 -> f32) ----
struct Batch {
    const float* A[8];
    const float* B[8];
    void*        Cc[8];
    const float* vec[8];
};

template<int EPI>
__global__ __launch_bounds__(256, 2)
void gemm128(Batch bt, int lda, int ldb, int ldc, int N, int K,
             const float* __restrict__ aux1, const float* __restrict__ aux2)
{
    __shared__ float2 As[2][16][128];
    __shared__ float  Bs[2][16][128];

    const int z = blockIdx.z;
    const float* __restrict__ A   = bt.A[z];
    const float* __restrict__ B   = bt.B[z];
    const float* __restrict__ vec = bt.vec[z];

    const int tid = threadIdx.x;
    const int bx = blockIdx.x, by = blockIdx.y;
    const int arow = tid >> 1,  acol = (tid & 1) * 8;
    const int brow = tid >> 4,  bcol = (tid & 15) * 8;
    const int tx = tid & 15,    ty = tid >> 4;

    unsigned long long acc[8][4];
    #pragma unroll
    for (int i = 0; i < 8; i++)
        #pragma unroll
        for (int j = 0; j < 4; j++) acc[i][j] = 0ULL;

    const float* Ap = A + (size_t)(by * 128 + arow) * lda + acol;
    const int gcolb = bx * 128 + bcol;

    float4 a0, a1, b0, b1;
    auto loadAB = [&](int k0) {
        a0 = *(const float4*)(Ap + k0);
        a1 = *(const float4*)(Ap + k0 + 4);
        const float* bp = B + (size_t)(k0 + brow) * ldb + gcolb;
        b0 = *(const float4*)bp;
        b1 = *(const float4*)(bp + 4);
    };
    auto storeAB = [&](int buf) {
        As[buf][acol + 0][arow] = make_float2(a0.x, a0.x);
        As[buf][acol + 1][arow] = make_float2(a0.y, a0.y);
        As[buf][acol + 2][arow] = make_float2(a0.z, a0.z);
        As[buf][acol + 3][arow] = make_float2(a0.w, a0.w);
        As[buf][acol + 4][arow] = make_float2(a1.x, a1.x);
        As[buf][acol + 5][arow] = make_float2(a1.y, a1.y);
        As[buf][acol + 6][arow] = make_float2(a1.z, a1.z);
        As[buf][acol + 7][arow] = make_float2(a1.w, a1.w);
        *(float4*)&Bs[buf][brow][bcol]     = b0;
        *(float4*)&Bs[buf][brow][bcol + 4] = b1;
    };

    loadAB(0);
    storeAB(0);
    __syncthreads();

    const int nt = K >> 4;
    for (int kt = 0; kt < nt; kt++) {
        const int cur = kt & 1;
        if (kt + 1 < nt) loadAB((kt + 1) << 4);

        #pragma unroll
        for (int kk = 0; kk < 16; kk++) {
            unsigned long long a2[8], b2[4];
            const ulonglong2* ap = (const ulonglong2*)&As[cur][kk][ty * 8];
            ulonglong2 w;
            w = ap[0]; a2[0] = w.x; a2[1] = w.y;
            w = ap[1]; a2[2] = w.x; a2[3] = w.y;
            w = ap[2]; a2[4] = w.x; a2[5] = w.y;
            w = ap[3]; a2[6] = w.x; a2[7] = w.y;
            const ulonglong2* bp2 = (const ulonglong2*)&Bs[cur][kk][tx * 8];
            w = bp2[0]; b2[0] = w.x; b2[1] = w.y;
            w = bp2[1]; b2[2] = w.x; b2[3] = w.y;
            #pragma unroll
            for (int i = 0; i < 8; i++)
                #pragma unroll
                for (int j = 0; j < 4; j++)
                    asm("fma.rn.f32x2 %0, %1, %2, %0;"
                        : "+l"(acc[i][j]) : "l"(a2[i]), "l"(b2[j]));
        }

        if (kt + 1 < nt) storeAB(cur ^ 1);
        __syncthreads();
    }

    #pragma unroll
    for (int i = 0; i < 8; i++) {
        const int row = by * 128 + ty * 8 + i;
        #pragma unroll
        for (int j = 0; j < 4; j++) {
            const int col = bx * 128 + tx * 8 + 2 * j;
            float v0 = __uint_as_float((unsigned)(acc[i][j] & 0xffffffffULL));
            float v1 = __uint_as_float((unsigned)(acc[i][j] >> 32));
            if (EPI == EPI_MIX) {
                size_t idx = (size_t)row * C_ + col;
                v0 = aux1[idx]     + aux2[idx]     * (vec[col]     + v0);
                v1 = aux1[idx + 1] + aux2[idx + 1] * (vec[col + 1] + v1);
                __nv_bfloat16 h0 = __float2bfloat16(v0);
                __nv_bfloat16 h1 = __float2bfloat16(v1);
                __nv_bfloat16 l0 = __float2bfloat16(v0 - __bfloat162float(h0));
                __nv_bfloat16 l1 = __float2bfloat16(v1 - __bfloat162float(h1));
                __nv_bfloat162 hh; hh.x = h0; hh.y = h1;
                __nv_bfloat162 ll; ll.x = l0; ll.y = l1;
                __nv_bfloat16* bout = (__nv_bfloat16*)bt.Cc[z];
                size_t base = (size_t)row * K3_;
                *(__nv_bfloat162*)&bout[base + col]          = hh;
                *(__nv_bfloat162*)&bout[base + C_ + col]     = hh;
                *(__nv_bfloat162*)&bout[base + 2 * C_ + col] = ll;
            } else {  // EPI_DECAY
                float* crow = (float*)bt.Cc[z] + (size_t)row * ldc;
                float lw0 = fmaxf(-expf(v0 + vec[col]), -5.0f);
                float lw1 = fmaxf(-expf(v1 + vec[col + 1]), -5.0f);
                *(float2*)&crow[col] = make_float2(expf(lw0), expf(lw1));
            }
        }
    }
}

// ---------------- token shift: writes sx (f32) + xxx (bf16 split) ----------------
__global__ void k_shift(const float* __restrict__ x, const float* __restrict__ state,
                        const unsigned char* __restrict__ ns,
                        const float* __restrict__ maa_x)
{
    int idx = blockIdx.x * blockDim.x + threadIdx.x;
    if (idx >= T_ * C_) return;
    int t = idx >> 11;
    int c = idx & 2047;
    float prev = (t == 0) ? state[c] : x[idx - C_];
    if (ns[t]) prev = 0.f;
    float s = prev - x[idx];
    g_sx[idx] = s;
    float v = x[idx] + s * maa_x[c];
    __nv_bfloat16 hi = __float2bfloat16(v);
    __nv_bfloat16 lo = __float2bfloat16(v - __bfloat162float(hi));
    size_t base = (size_t)t * K3_;
    g_ba_xxx[base + c]          = hi;
    g_ba_xxx[base + C_ + c]     = hi;
    g_ba_xxx[base + 2 * C_ + c] = lo;
}

// ---------------- the RWKV scan v2: batched output reduction ----------------
__global__ __launch_bounds__(512)
void k_scan(const float* __restrict__ state, const unsigned char* __restrict__ ns,
            __nv_bfloat16* __restrict__ out_split)
{
    const int h = blockIdx.x;
    const int tid = threadIdx.x;
    const int vcol = tid >> 3;
    const int kg = tid & 7;

    unsigned long long s2[4];
    #pragma unroll
    for (int j2 = 0; j2 < 4; j2++) {
        float slo = state[C_ + h * 4096 + (kg * 8 + 2 * j2) * 64 + vcol];
        float shi = state[C_ + h * 4096 + (kg * 8 + 2 * j2 + 1) * 64 + vcol];
        asm("mov.b64 %0, {%1, %2};" : "=l"(s2[j2]) : "f"(slo), "f"(shi));
    }

    __shared__ float sh[2][4 * 64];
    __shared__ float gbuf[16][64];
    __shared__ float pbuf[16][512];
    __shared__ unsigned char nsh[T_];
    for (int i = tid; i < T_; i += 512) nsh[i] = ns[i];

    const int a  = tid >> 6;
    const int li = tid & 63;
    const bool loader = (a < 5);
    const size_t baseC  = (size_t)h * 64 + li;
    const size_t baseKV = (size_t)(h >> 2) * 64 + li;

    auto gload = [&](int t) -> float {
        switch (a) {
            case 0:  return g_r[(size_t)t * C_ + baseC];
            case 1: {
                float kv = g_k [(size_t)t * 512 + baseKV];
                float ew = g_ew[(size_t)t * C_ + baseC];
                return kv * (1.f - ew);
            }
            case 2:  return g_ew[(size_t)t * C_ + baseC];
            case 3:  return g_v [(size_t)t * 512 + baseKV];
            default: return g_gate[(size_t)t * C_ + baseC];
        }
    };

    float rr[8];
    if (loader) {
        #pragma unroll
        for (int p = 0; p < 8; p++) rr[p] = gload(p);
        if (a < 4) sh[0][a * 64 + li] = rr[0];
        else       gbuf[0][li] = rr[0];
    }
    __syncthreads();

    #pragma unroll 8
    for (int t = 0; t < T_; t++) {
        if (loader) {
            if (t + 8 < T_) rr[(t + 8) & 7] = gload(t + 8);
            if (t + 1 < T_) {
                float val = rr[(t + 1) & 7];
                if (a < 4) sh[(t + 1) & 1][a * 64 + li] = val;
                else       gbuf[(t + 1) & 15][li] = val;
            }
        }
        const float* S = sh[t & 1];

        float vv = S[3 * 64 + vcol];
        unsigned long long vv2;
        asm("mov.b64 %0, {%1, %1};" : "=l"(vv2) : "f"(vv));

        const bool reset = (nsh[t] != 0);

        const ulonglong2* rp = (const ulonglong2*)&S[0 * 64 + kg * 8];
        const ulonglong2* kp = (const ulonglong2*)&S[1 * 64 + kg * 8];
        const ulonglong2* wp = (const ulonglong2*)&S[2 * 64 + kg * 8];
        ulonglong2 rA = rp[0], rB = rp[1];
        ulonglong2 kA = kp[0], kB = kp[1];
        ulonglong2 wA = wp[0], wB = wp[1];
        unsigned long long r2[4] = { rA.x, rA.y, rB.x, rB.y };
        unsigned long long k2[4] = { kA.x, kA.y, kB.x, kB.y };
        unsigned long long w2[4] = { wA.x, wA.y, wB.x, wB.y };

        unsigned long long ps2 = 0ULL;
        #pragma unroll
        for (int j2 = 0; j2 < 4; j2++) {
            if (reset) s2[j2] = 0ULL;
            unsigned long long kv2;
            asm("mul.rn.f32x2 %0, %1, %2;"     : "=l"(kv2)    : "l"(k2[j2]), "l"(vv2));
            asm("fma.rn.f32x2 %0, %1, %2, %3;" : "=l"(s2[j2]) : "l"(s2[j2]), "l"(w2[j2]), "l"(kv2));
            asm("fma.rn.f32x2 %0, %1, %2, %0;" : "+l"(ps2)    : "l"(r2[j2]), "l"(s2[j2]));
        }

        float plo = __uint_as_float((unsigned)(ps2 & 0xffffffffULL));
        float phi = __uint_as_float((unsigned)(ps2 >> 32));
        pbuf[t & 15][tid] = plo + phi;
        __syncthreads();

        if ((t & 7) == 7) {
            const int st = tid >> 6;
            const int vc = tid & 63;
            const int slot = (t - 7 + st) & 15;
            const float4* p4 = (const float4*)&pbuf[slot][vc * 8];
            float4 x0 = p4[0], x1 = p4[1];
            float o = ((x0.x + x0.y) + (x0.z + x0.w)) + ((x1.x + x1.y) + (x1.z + x1.w));
            o *= gbuf[slot][vc];
            const int trow = t - 7 + st;
            __nv_bfloat16 hi = __float2bfloat16(o);
            __nv_bfloat16 lo = __float2bfloat16(o - __bfloat162float(hi));
            size_t base = (size_t)trow * K3_;
            int c = h * 64 + vc;
            out_split[base + c]          = hi;
            out_split[base + C_ + c]     = hi;
            out_split[base + 2 * C_ + c] = lo;
        }
    }

    #pragma unroll
    for (int j2 = 0; j2 < 4; j2++) {
        float slo = __uint_as_float((unsigned)(s2[j2] & 0xffffffffULL));
        float shi = __uint_as_float((unsigned)(s2[j2] >> 32));
        g_sfin[h * 4096 + (kg * 8 + 2 * j2) * 64 + vcol]     = slo;
        g_sfin[h * 4096 + (kg * 8 + 2 * j2 + 1) * 64 + vcol] = shi;
    }
}

// ---------------- new_state writer ----------------
__global__ void k_state(float* __restrict__ dout, const float* __restrict__ x,
                        const int* __restrict__ lenp)
{
    int idx = blockIdx.x * blockDim.x + threadIdx.x;
    int L = lenp ? lenp[0] : T_;
    if (idx < C_)
        dout[(size_t)T_ * C_ + idx] = x[(size_t)(L - 1) * C_ + idx];
    if (idx < H_ * S_ * S_)
        dout[(size_t)T_ * C_ + C_ + idx] = g_sfin[idx];
}

// ---------------- host-side orchestration ----------------
template <typename Sym>
static void* devaddr_v(Sym& sym) {
    void* p = nullptr;
    cudaGetSymbolAddress(&p, sym);
    return p;
}

#define HG_SMEM (3 * 49152)

extern "C" void kernel_launch(void* const* d_in, const int* in_sizes, int n_in,
                              void* d_out, int out_size)
{
    int i = 0;
    const float* x       = (const float*)d_in[i++];
    const float* state   = (const float*)d_in[i++];
    const unsigned char* ns = (const unsigned char*)d_in[i++];
    const int* lenp = nullptr;
    if (n_in >= 20) { lenp = (const int*)d_in[i++]; }
    const float* maa_x = (const float*)d_in[i++];
    const float* maa_r = (const float*)d_in[i++];
    const float* maa_k = (const float*)d_in[i++];
    const float* maa_v = (const float*)d_in[i++];
    const float* maa_w = (const float*)d_in[i++];
    const float* maa_g = (const float*)d_in[i++];
    const float* maa_w1 = (const float*)d_in[i++];  // [C, 160]
    const float* maa_w2 = (const float*)d_in[i++];  // [5, 32, C]
    const float* tdecay = (const float*)d_in[i++];  // [C]
    const float* dec_w1 = (const float*)d_in[i++];  // [C, 64]
    const float* dec_w2 = (const float*)d_in[i++];  // [64, C]
    const float* Wq = (const float*)d_in[i++];      // [C, C]
    const float* Wk = (const float*)d_in[i++];      // [C, 512]
    const float* Wv = (const float*)d_in[i++];      // [C, 512]
    const float* Wg = (const float*)d_in[i++];      // [C, C]
    const float* Wo = (const float*)d_in[i++];      // [C, C]
    float* dout = (float*)d_out;

    float* p_sx   = (float*)devaddr_v(g_sx);
    float* p_t1   = (float*)devaddr_v(g_t1);
    float* p_t2   = (float*)devaddr_v(g_t2);
    float* p_r    = (float*)devaddr_v(g_r);
    float* p_k    = (float*)devaddr_v(g_k);
    float* p_v    = (float*)devaddr_v(g_v);
    float* p_ew   = (float*)devaddr_v(g_ew);
    float* p_gate = (float*)devaddr_v(g_gate);
    float* p_part = (float*)devaddr_v(g_part);
    __nv_bfloat16* p_ba_xxx = (__nv_bfloat16*)devaddr_v(g_ba_xxx);
    __nv_bfloat16* p_ba_r   = (__nv_bfloat16*)devaddr_v(g_ba_r);
    __nv_bfloat16* p_ba_k   = (__nv_bfloat16*)devaddr_v(g_ba_k);
    __nv_bfloat16* p_ba_v   = (__nv_bfloat16*)devaddr_v(g_ba_v);
    __nv_bfloat16* p_ba_w   = (__nv_bfloat16*)devaddr_v(g_ba_w);
    __nv_bfloat16* p_ba_g   = (__nv_bfloat16*)devaddr_v(g_ba_g);
    __nv_bfloat16* p_bwA  = (__nv_bfloat16*)devaddr_v(g_bwA);
    __nv_bfloat16* p_bwB  = (__nv_bfloat16*)devaddr_v(g_bwB);
    __nv_bfloat16* p_bw1  = (__nv_bfloat16*)devaddr_v(g_bw1);
    __nv_bfloat16* p_bw2  = (__nv_bfloat16*)devaddr_v(g_bw2);
    __nv_bfloat16* p_bws1 = (__nv_bfloat16*)devaddr_v(g_bws1);
    __nv_bfloat16* p_bws2 = (__nv_bfloat16*)devaddr_v(g_bws2);

    cudaFuncSetAttribute(hgemm, cudaFuncAttributeMaxDynamicSharedMemorySize, HG_SMEM);

    const int EW = 256;
    const int GE = (T_ * C_ + EW - 1) / EW;
    dim3 blk(256);
    dim3 cw(32, 8);

    // 0) weight conversions
    k_conv_w<<<dim3(C_ / 32, 64), cw>>>(Wq, p_bwA, C_);
    k_conv_w<<<dim3(C_ / 32, 64), cw>>>(Wg, p_bwB, C_);
    k_conv_w<<<dim3(512 / 32, 64), cw>>>(Wk, p_bw1, HKV_ * S_);
    k_conv_w<<<dim3(512 / 32, 64), cw>>>(Wv, p_bw2, HKV_ * S_);
    k_conv_w<<<dim3(256 / 32, 64), cw>>>(maa_w1, p_bws1, 5 * LMAA_);
    k_conv_w<<<dim3(256 / 32, 64), cw>>>(dec_w1, p_bws2, LDEC_);

    // 1) token shift -> sx (f32) + ba_xxx (bf16 split)
    k_shift<<<GE, EW>>>(x, state, ns, maa_x);

    // 2) t1 = tanh(xxx @ maa_w1) [T,160]: split-K 4 + reduce
    {
        TB tb = {};
        tb.A[0] = p_ba_xxx; tb.B[0] = p_bws1; tb.Cc[0] = p_part;
        tb.N[0] = 5 * LMAA_; tb.ldc[0] = 5 * LMAA_; tb.epi[0] = EPI_NONE;
        hgemm<<<dim3(1, 16, SPLITK), blk, HG_SMEM>>>(tb, 96 / SPLITK, T_ * 5 * LMAA_);
        int n = T_ * 5 * LMAA_;
        k_red_tanh<<<(n + EW - 1) / EW, EW>>>(p_part, p_t1, n, n);
    }

    // 3) MIX (FFMA2, K=32): writes 5 bf16-split activation buffers
    {
        Batch bt = {};
        const float* vecs[5] = { maa_r, maa_k, maa_v, maa_w, maa_g };
        void* outs[5] = { p_ba_r, p_ba_k, p_ba_v, p_ba_w, p_ba_g };
        for (int z = 0; z < 5; z++) {
            bt.A[z]  = p_t1 + z * LMAA_;
            bt.B[z]  = maa_w2 + (size_t)z * LMAA_ * C_;
            bt.Cc[z] = outs[z];
            bt.vec[z] = vecs[z];
        }
        gemm128<EPI_MIX><<<dim3(C_ / 128, T_ / 128, 5), blk>>>(bt, 5 * LMAA_, C_, C_, C_, LMAA_, x, p_sx);
    }

    // 4) r + gate + k + v in ONE launch (z=4)
    {
        TB tb = {};
        tb.A[0] = p_ba_r; tb.B[0] = p_bwA; tb.Cc[0] = p_r;    tb.N[0] = C_;  tb.ldc[0] = C_;  tb.epi[0] = EPI_NONE;
        tb.A[1] = p_ba_g; tb.B[1] = p_bwB; tb.Cc[1] = p_gate; tb.N[1] = C_;  tb.ldc[1] = C_;  tb.epi[1] = EPI_SIG;
        tb.A[2] = p_ba_k; tb.B[2] = p_bw1; tb.Cc[2] = p_k;    tb.N[2] = 512; tb.ldc[2] = 512; tb.epi[2] = EPI_NONE;
        tb.A[3] = p_ba_v; tb.B[3] = p_bw2; tb.Cc[3] = p_v;    tb.N[3] = 512; tb.ldc[3] = 512; tb.epi[3] = EPI_NONE;
        hgemm<<<dim3(8, 16, 4), blk, HG_SMEM>>>(tb, 96, 0);
    }

    // 5) t2 = tanh(xw @ dec_w1) [T,64]: split-K 4 + reduce
    {
        TB tb = {};
        tb.A[0] = p_ba_w; tb.B[0] = p_bws2; tb.Cc[0] = p_part;
        tb.N[0] = LDEC_; tb.ldc[0] = LDEC_; tb.epi[0] = EPI_NONE;
        hgemm<<<dim3(1, 16, SPLITK), blk, HG_SMEM>>>(tb, 96 / SPLITK, T_ * LDEC_);
        int n = T_ * LDEC_;
        k_red_tanh<<<(n + EW - 1) / EW, EW>>>(p_part, p_t2, n, n);
    }

    // 6) ew = exp(max(-exp(t2@dec_w2 + tdecay), -5)) (FFMA2, K=64)
    {
        Batch bt = {};
        bt.A[0] = p_t2; bt.B[0] = dec_w2; bt.Cc[0] = p_ew; bt.vec[0] = tdecay;
        gemm128<EPI_DECAY><<<dim3(C_ / 128, T_ / 128, 1), blk>>>(bt, LDEC_, C_, C_, C_, LDEC_, nullptr, nullptr);
    }

    // 7) Wo conversion (bwA free after step 4)
    k_conv_w<<<dim3(C_ / 32, 64), cw>>>(Wo, p_bwA, C_);

    // 8) scan: writes gated output as bf16 split into ba_r (reused)
    k_scan<<<H_, 512>>>(state, ns, p_ba_r);

    // 9) final projection: dout = (out*gate) @ Wo
    {
        TB tb = {};
        tb.A[0] = p_ba_r; tb.B[0] = p_bwA; tb.Cc[0] = dout;
        tb.N[0] = C_; tb.ldc[0] = C_; tb.epi[0] = EPI_NONE;
        hgemm<<<dim3(8, 16, 1), blk, HG_SMEM>>>(tb, 96, 0);
    }

    // 10) new_state (only if the harness expects both outputs)
    if (out_size >= T_ * C_ + (S_ + 1) * C_) {
        int n = H_ * S_ * S_;
        k_state<<<(n + EW - 1) / EW, EW>>>(dout, x, lenp);
    }
}

// round 12
// speedup vs baseline: 1.1184x; 1.1184x over previous
#include <cuda_runtime.h>
#include <cuda_bf16.h>
#include <math.h>
#include <stdint.h>

#define T_ 2048
#define C_ 2048
#define H_ 32
#define S_ 64
#define HKV_ 8
#define LMAA_ 32
#define LDEC_ 64
#define K3_ (3 * C_)   // 6144
#define SPLITK 4

// ---------------- f32 scratch ----------------
__device__ float g_sx [T_*C_];
__device__ float g_t1 [T_*5*LMAA_];
__device__ float g_t2 [T_*LDEC_];
__device__ float g_r  [T_*C_];
__device__ float g_k  [T_*HKV_*S_];
__device__ float g_v  [T_*HKV_*S_];
__device__ float g_ew [T_*C_];
__device__ float g_gate[T_*C_];
__device__ float g_sfin[H_*S_*S_];
__device__ float g_part[SPLITK * T_ * (5*LMAA_ + LDEC_)];

// ---------------- bf16 3-split buffers (A'=[hi|hi|lo], W'=[hi|lo|hi]) ----------------
__device__ __align__(128) __nv_bfloat16 g_ba_xxx[(size_t)T_ * K3_];
__device__ __align__(128) __nv_bfloat16 g_ba_r  [(size_t)T_ * K3_];   // xr, later reused for out
__device__ __align__(128) __nv_bfloat16 g_ba_k  [(size_t)T_ * K3_];
__device__ __align__(128) __nv_bfloat16 g_ba_v  [(size_t)T_ * K3_];
__device__ __align__(128) __nv_bfloat16 g_ba_w  [(size_t)T_ * K3_];
__device__ __align__(128) __nv_bfloat16 g_ba_g  [(size_t)T_ * K3_];
__device__ __align__(128) __nv_bfloat16 g_bwA[(size_t)2048 * K3_];    // Wq
__device__ __align__(128) __nv_bfloat16 g_bwB[(size_t)2048 * K3_];    // Wg
__device__ __align__(128) __nv_bfloat16 g_bwC[(size_t)2048 * K3_];    // Wo
__device__ __align__(128) __nv_bfloat16 g_bw1[(size_t)512 * K3_];     // Wk
__device__ __align__(128) __nv_bfloat16 g_bw2[(size_t)512 * K3_];     // Wv
__device__ __align__(128) __nv_bfloat16 g_bws1[(size_t)256 * K3_];    // maa_w1 (160->256)
__device__ __align__(128) __nv_bfloat16 g_bws2[(size_t)256 * K3_];    // dec_w1 (64->256)

// ---------------- epilogue ids ----------------
#define EPI_NONE  0
#define EPI_TANH  1
#define EPI_SIG   2
#define EPI_MIX   3
#define EPI_DECAY 4

// ---------------- mma.sync helpers ----------------
__device__ __forceinline__ uint32_t smem_u32(const void* p) {
    uint32_t a;
    asm("{ .reg .u64 t; cvta.to.shared.u64 t, %1; cvt.u32.u64 %0, t; }" : "=r"(a) : "l"(p));
    return a;
}
__device__ __forceinline__ void cp_async16(uint32_t saddr, const void* g) {
    asm volatile("cp.async.cg.shared.global [%0], [%1], 16;" :: "r"(saddr), "l"(g) : "memory");
}
__device__ __forceinline__ void ldmatrix_x4(uint32_t* r, uint32_t addr) {
    asm volatile("ldmatrix.sync.aligned.m8n8.x4.shared.b16 {%0,%1,%2,%3}, [%4];"
        : "=r"(r[0]), "=r"(r[1]), "=r"(r[2]), "=r"(r[3]) : "r"(addr));
}
__device__ __forceinline__ void mma16816(float* c, const uint32_t* a, uint32_t b0, uint32_t b1) {
    asm volatile("mma.sync.aligned.m16n8k16.row.col.f32.bf16.bf16.f32 "
        "{%0,%1,%2,%3}, {%4,%5,%6,%7}, {%8,%9}, {%0,%1,%2,%3};"
        : "+f"(c[0]), "+f"(c[1]), "+f"(c[2]), "+f"(c[3])
        : "r"(a[0]), "r"(a[1]), "r"(a[2]), "r"(a[3]), "r"(b0), "r"(b1));
}

struct TB {
    const __nv_bfloat16* A[4];
    const __nv_bfloat16* B[4];
    float*               Cc[4];
    int N[4];
    int ldc[4];
    int epi[4];
};

// ---------------- HMMA bf16 GEMM v1: C = A'[M,K'] @ B'[N,K']^T ----------------
// 128x128 CTA tile, 8 warps (2m x 4n), warp 64x32 m16n8k16, BK=64, 3-stage cp.async.
// splitStride>0: split-K mode (z = split idx, entry 0, kc0 = z*nch, C += z*splitStride).
__global__ __launch_bounds__(256, 2)
void hgemm(TB bt, int nch, int splitStride)
{
    const int z = blockIdx.z;
    const __nv_bfloat16* __restrict__ Ag;
    const __nv_bfloat16* __restrict__ Bg;
    float* __restrict__ Cg;
    int N, ldc, epi, kc0 = 0;
    if (splitStride > 0) {
        Ag = bt.A[0]; Bg = bt.B[0]; N = bt.N[0]; ldc = bt.ldc[0]; epi = bt.epi[0];
        Cg = bt.Cc[0] + (size_t)z * splitStride;
        kc0 = z * nch;
    } else {
        Ag = bt.A[z]; Bg = bt.B[z]; Cg = bt.Cc[z];
        N = bt.N[z]; ldc = bt.ldc[z]; epi = bt.epi[z];
    }
    if (blockIdx.x * 128 >= N) return;

    extern __shared__ char smem[];
    const uint32_t sbase = smem_u32(smem);   // 3 stages x (A 16KB | B 16KB)

    const int tid  = threadIdx.x;
    const int lane = tid & 31;
    const int wid  = tid >> 5;
    const int wm   = wid >> 2;    // 0..1
    const int wn   = wid & 3;     // 0..3
    const int bx = blockIdx.x, by = blockIdx.y;

    float acc[4][4][4];
    #pragma unroll
    for (int i = 0; i < 4; i++)
        #pragma unroll
        for (int j = 0; j < 4; j++)
            #pragma unroll
            for (int k = 0; k < 4; k++) acc[i][j][k] = 0.f;

    const __nv_bfloat16* Abase = Ag + (size_t)(by * 128) * K3_;
    const __nv_bfloat16* Bbase = Bg + (size_t)(bx * 128) * K3_;

    auto load_stage = [&](int kt, int s) {
        const uint32_t sa = sbase + s * 32768;
        const __nv_bfloat16* Agk = Abase + (size_t)(kc0 + kt) * 64;
        const __nv_bfloat16* Bgk = Bbase + (size_t)(kc0 + kt) * 64;
        #pragma unroll
        for (int q = 0; q < 4; q++) {
            const int c = q * 256 + tid;
            const int row = c >> 3, j = c & 7;
            uint32_t off = (uint32_t)(row * 128 + j * 16);
            off ^= (off >> 3) & 0x70;
            cp_async16(sa + off,         Agk + (size_t)row * K3_ + j * 8);
            cp_async16(sa + 16384 + off, Bgk + (size_t)row * K3_ + j * 8);
        }
        asm volatile("cp.async.commit_group;" ::: "memory");
    };

    const int a_roff = (wm * 64 + (lane & 15)) * 128 + (lane >> 4) * 16;
    const int b_roff = (wn * 32 + (lane & 7) + ((lane >> 4) << 3)) * 128 + ((lane >> 3) & 1) * 16;

    auto compute = [&](int s) {
        const uint32_t sa = sbase + s * 32768;
        const uint32_t sbb = sa + 16384;
        #pragma unroll
        for (int ks = 0; ks < 4; ks++) {
            uint32_t bf2[2][4];
            #pragma unroll
            for (int nt2 = 0; nt2 < 2; nt2++) {
                uint32_t off = (uint32_t)(b_roff + nt2 * 16 * 128 + ks * 32);
                off ^= (off >> 3) & 0x70;
                ldmatrix_x4(bf2[nt2], sbb + off);
            }
            uint32_t af[4][4];
            #pragma unroll
            for (int mt = 0; mt < 4; mt++) {
                uint32_t off = (uint32_t)(a_roff + mt * 16 * 128 + ks * 32);
                off ^= (off >> 3) & 0x70;
                ldmatrix_x4(af[mt], sa + off);
            }
            #pragma unroll
            for (int mt = 0; mt < 4; mt++)
                #pragma unroll
                for (int nt = 0; nt < 4; nt++)
                    mma16816(acc[mt][nt], af[mt],
                             bf2[nt >> 1][(nt & 1) * 2], bf2[nt >> 1][(nt & 1) * 2 + 1]);
        }
    };

    load_stage(0, 0);
    load_stage(1, 1);

    for (int kt = 0; kt < nch; kt++) {
        asm volatile("cp.async.wait_group 1;" ::: "memory");
        __syncthreads();
        if (kt + 2 < nch) load_stage(kt + 2, (kt + 2) % 3);
        else asm volatile("cp.async.commit_group;" ::: "memory");
        compute(kt % 3);
    }

    // epilogue (runtime epi: NONE / TANH / SIG)
    #pragma unroll
    for (int mt = 0; mt < 4; mt++) {
        #pragma unroll
        for (int hrow = 0; hrow < 2; hrow++) {
            const int row = by * 128 + wm * 64 + mt * 16 + hrow * 8 + (lane >> 2);
            float* crow = Cg + (size_t)row * ldc;
            #pragma unroll
            for (int nt = 0; nt < 4; nt++) {
                const int col = bx * 128 + wn * 32 + nt * 8 + (lane & 3) * 2;
                if (col >= N) continue;
                float v0 = acc[mt][nt][hrow * 2 + 0];
                float v1 = acc[mt][nt][hrow * 2 + 1];
                if (epi == EPI_TANH) { v0 = tanhf(v0); v1 = tanhf(v1); }
                else if (epi == EPI_SIG) { v0 = 1.f/(1.f+expf(-v0)); v1 = 1.f/(1.f+expf(-v1)); }
                *(float2*)&crow[col] = make_float2(v0, v1);
            }
        }
    }
}

// ---------------- split-K reducer + tanh ----------------
__global__ void k_red_tanh(const float* __restrict__ part, float* __restrict__ out,
                           int n, int stride)
{
    int i = blockIdx.x * blockDim.x + threadIdx.x;
    if (i >= n) return;
    float s = part[i] + part[(size_t)stride + i]
            + part[(size_t)2 * stride + i] + part[(size_t)3 * stride + i];
    out[i] = tanhf(s);
}

// ---------------- batched weight conversion (ALL weights, one launch) ----------------
// src[2048 x N] f32 -> dst[Npad x 6144] bf16 rows n: [hi | lo | hi], transposed.
struct CB {
    const float*   src[7];
    __nv_bfloat16* dst[7];
    int            N[7];       // true N
    int            xt[7];      // x-tiles (Npad/32)
};

__global__ void k_conv_all(CB cb)
{
    __shared__ float tile[32][33];
    int bx = blockIdx.x;
    int w = 0;
    while (bx >= cb.xt[w]) { bx -= cb.xt[w]; w++; }
    const float* __restrict__ src = cb.src[w];
    __nv_bfloat16* __restrict__ dst = cb.dst[w];
    const int N = cb.N[w];

    const int n0 = bx * 32;
    const int k0 = blockIdx.y * 32;
    const int tx = threadIdx.x, ty = threadIdx.y;  // (32, 8)
    #pragma unroll
    for (int yy = 0; yy < 32; yy += 8) {
        int n = n0 + tx, k = k0 + ty + yy;
        tile[ty + yy][tx] = (n < N) ? src[(size_t)k * N + n] : 0.f;
    }
    __syncthreads();
    #pragma unroll
    for (int yy = 0; yy < 32; yy += 8) {
        int n = n0 + ty + yy;
        int k = k0 + tx;
        float a = tile[tx][ty + yy];
        __nv_bfloat16 hi = __float2bfloat16(a);
        __nv_bfloat16 lo = __float2bfloat16(a - __bfloat162float(hi));
        size_t base = (size_t)n * K3_;
        dst[base + k] = hi;
        dst[base + C_ + k] = lo;
        dst[base + 2 * C_ + k] = hi;
    }
}

// ---------------- FFMA2 GEMM (small-K: MIX K=32 -> bf16 split out, DECAY K=64 -> f32) ----
struct Batch {
    const float* A[8];
    const float* B[8];
    void*        Cc[8];
    const float* vec[8];
};

template<int EPI>
__global__ __launch_bounds__(256, 2)
void gemm128(Batch bt, int lda, int ldb, int ldc, int N, int K,
             const float* __restrict__ aux1, const float* __restrict__ aux2)
{
    __shared__ float2 As[2][16][128];
    __shared__ float  Bs[2][16][128];

    const int z = blockIdx.z;
    const float* __restrict__ A   = bt.A[z];
    const float* __restrict__ B   = bt.B[z];
    const float* __restrict__ vec = bt.vec[z];

    const int tid = threadIdx.x;
    const int bx = blockIdx.x, by = blockIdx.y;
    const int arow = tid >> 1,  acol = (tid & 1) * 8;
    const int brow = tid >> 4,  bcol = (tid & 15) * 8;
    const int tx = tid & 15,    ty = tid >> 4;

    unsigned long long acc[8][4];
    #pragma unroll
    for (int i = 0; i < 8; i++)
        #pragma unroll
        for (int j = 0; j < 4; j++) acc[i][j] = 0ULL;

    const float* Ap = A + (size_t)(by * 128 + arow) * lda + acol;
    const int gcolb = bx * 128 + bcol;

    float4 a0, a1, b0, b1;
    auto loadAB = [&](int k0) {
        a0 = *(const float4*)(Ap + k0);
        a1 = *(const float4*)(Ap + k0 + 4);
        const float* bp = B + (size_t)(k0 + brow) * ldb + gcolb;
        b0 = *(const float4*)bp;
        b1 = *(const float4*)(bp + 4);
    };
    auto storeAB = [&](int buf) {
        As[buf][acol + 0][arow] = make_float2(a0.x, a0.x);
        As[buf][acol + 1][arow] = make_float2(a0.y, a0.y);
        As[buf][acol + 2][arow] = make_float2(a0.z, a0.z);
        As[buf][acol + 3][arow] = make_float2(a0.w, a0.w);
        As[buf][acol + 4][arow] = make_float2(a1.x, a1.x);
        As[buf][acol + 5][arow] = make_float2(a1.y, a1.y);
        As[buf][acol + 6][arow] = make_float2(a1.z, a1.z);
        As[buf][acol + 7][arow] = make_float2(a1.w, a1.w);
        *(float4*)&Bs[buf][brow][bcol]     = b0;
        *(float4*)&Bs[buf][brow][bcol + 4] = b1;
    };

    loadAB(0);
    storeAB(0);
    __syncthreads();

    const int nt = K >> 4;
    for (int kt = 0; kt < nt; kt++) {
        const int cur = kt & 1;
        if (kt + 1 < nt) loadAB((kt + 1) << 4);

        #pragma unroll
        for (int kk = 0; kk < 16; kk++) {
            unsigned long long a2[8], b2[4];
            const ulonglong2* ap = (const ulonglong2*)&As[cur][kk][ty * 8];
            ulonglong2 w;
            w = ap[0]; a2[0] = w.x; a2[1] = w.y;
            w = ap[1]; a2[2] = w.x; a2[3] = w.y;
            w = ap[2]; a2[4] = w.x; a2[5] = w.y;
            w = ap[3]; a2[6] = w.x; a2[7] = w.y;
            const ulonglong2* bp2 = (const ulonglong2*)&Bs[cur][kk][tx * 8];
            w = bp2[0]; b2[0] = w.x; b2[1] = w.y;
            w = bp2[1]; b2[2] = w.x; b2[3] = w.y;
            #pragma unroll
            for (int i = 0; i < 8; i++)
                #pragma unroll
                for (int j = 0; j < 4; j++)
                    asm("fma.rn.f32x2 %0, %1, %2, %0;"
                        : "+l"(acc[i][j]) : "l"(a2[i]), "l"(b2[j]));
        }

        if (kt + 1 < nt) storeAB(cur ^ 1);
        __syncthreads();
    }

    #pragma unroll
    for (int i = 0; i < 8; i++) {
        const int row = by * 128 + ty * 8 + i;
        #pragma unroll
        for (int j = 0; j < 4; j++) {
            const int col = bx * 128 + tx * 8 + 2 * j;
            float v0 = __uint_as_float((unsigned)(acc[i][j] & 0xffffffffULL));
            float v1 = __uint_as_float((unsigned)(acc[i][j] >> 32));
            if (EPI == EPI_MIX) {
                size_t idx = (size_t)row * C_ + col;
                v0 = aux1[idx]     + aux2[idx]     * (vec[col]     + v0);
                v1 = aux1[idx + 1] + aux2[idx + 1] * (vec[col + 1] + v1);
                __nv_bfloat16 h0 = __float2bfloat16(v0);
                __nv_bfloat16 h1 = __float2bfloat16(v1);
                __nv_bfloat16 l0 = __float2bfloat16(v0 - __bfloat162float(h0));
                __nv_bfloat16 l1 = __float2bfloat16(v1 - __bfloat162float(h1));
                __nv_bfloat162 hh; hh.x = h0; hh.y = h1;
                __nv_bfloat162 ll; ll.x = l0; ll.y = l1;
                __nv_bfloat16* bout = (__nv_bfloat16*)bt.Cc[z];
                size_t base = (size_t)row * K3_;
                *(__nv_bfloat162*)&bout[base + col]          = hh;
                *(__nv_bfloat162*)&bout[base + C_ + col]     = hh;
                *(__nv_bfloat162*)&bout[base + 2 * C_ + col] = ll;
            } else {  // EPI_DECAY
                float* crow = (float*)bt.Cc[z] + (size_t)row * ldc;
                float lw0 = fmaxf(-expf(v0 + vec[col]), -5.0f);
                float lw1 = fmaxf(-expf(v1 + vec[col + 1]), -5.0f);
                *(float2*)&crow[col] = make_float2(expf(lw0), expf(lw1));
            }
        }
    }
}

// ---------------- token shift: writes sx (f32) + xxx (bf16 split) ----------------
__global__ void k_shift(const float* __restrict__ x, const float* __restrict__ state,
                        const unsigned char* __restrict__ ns,
                        const float* __restrict__ maa_x)
{
    int idx = blockIdx.x * blockDim.x + threadIdx.x;
    if (idx >= T_ * C_) return;
    int t = idx >> 11;
    int c = idx & 2047;
    float prev = (t == 0) ? state[c] : x[idx - C_];
    if (ns[t]) prev = 0.f;
    float s = prev - x[idx];
    g_sx[idx] = s;
    float v = x[idx] + s * maa_x[c];
    __nv_bfloat16 hi = __float2bfloat16(v);
    __nv_bfloat16 lo = __float2bfloat16(v - __bfloat162float(hi));
    size_t base = (size_t)t * K3_;
    g_ba_xxx[base + c]          = hi;
    g_ba_xxx[base + C_ + c]     = hi;
    g_ba_xxx[base + 2 * C_ + c] = lo;
}

// ---------------- the RWKV scan (batched output reduction) ----------------
__global__ __launch_bounds__(512)
void k_scan(const float* __restrict__ state, const unsigned char* __restrict__ ns,
            __nv_bfloat16* __restrict__ out_split)
{
    const int h = blockIdx.x;
    const int tid = threadIdx.x;
    const int vcol = tid >> 3;
    const int kg = tid & 7;

    unsigned long long s2[4];
    #pragma unroll
    for (int j2 = 0; j2 < 4; j2++) {
        float slo = state[C_ + h * 4096 + (kg * 8 + 2 * j2) * 64 + vcol];
        float shi = state[C_ + h * 4096 + (kg * 8 + 2 * j2 + 1) * 64 + vcol];
        asm("mov.b64 %0, {%1, %2};" : "=l"(s2[j2]) : "f"(slo), "f"(shi));
    }

    __shared__ float sh[2][4 * 64];
    __shared__ float gbuf[16][64];
    __shared__ float pbuf[16][512];
    __shared__ unsigned char nsh[T_];
    for (int i = tid; i < T_; i += 512) nsh[i] = ns[i];

    const int a  = tid >> 6;
    const int li = tid & 63;
    const bool loader = (a < 5);
    const size_t baseC  = (size_t)h * 64 + li;
    const size_t baseKV = (size_t)(h >> 2) * 64 + li;

    auto gload = [&](int t) -> float {
        switch (a) {
            case 0:  return g_r[(size_t)t * C_ + baseC];
            case 1: {
                float kv = g_k [(size_t)t * 512 + baseKV];
                float ew = g_ew[(size_t)t * C_ + baseC];
                return kv * (1.f - ew);
            }
            case 2:  return g_ew[(size_t)t * C_ + baseC];
            case 3:  return g_v [(size_t)t * 512 + baseKV];
            default: return g_gate[(size_t)t * C_ + baseC];
        }
    };

    float rr[8];
    if (loader) {
        #pragma unroll
        for (int p = 0; p < 8; p++) rr[p] = gload(p);
        if (a < 4) sh[0][a * 64 + li] = rr[0];
        else       gbuf[0][li] = rr[0];
    }
    __syncthreads();

    #pragma unroll 8
    for (int t = 0; t < T_; t++) {
        if (loader) {
            if (t + 8 < T_) rr[(t + 8) & 7] = gload(t + 8);
            if (t + 1 < T_) {
                float val = rr[(t + 1) & 7];
                if (a < 4) sh[(t + 1) & 1][a * 64 + li] = val;
                else       gbuf[(t + 1) & 15][li] = val;
            }
        }
        const float* S = sh[t & 1];

        float vv = S[3 * 64 + vcol];
        unsigned long long vv2;
        asm("mov.b64 %0, {%1, %1};" : "=l"(vv2) : "f"(vv));

        const bool reset = (nsh[t] != 0);

        const ulonglong2* rp = (const ulonglong2*)&S[0 * 64 + kg * 8];
        const ulonglong2* kp = (const ulonglong2*)&S[1 * 64 + kg * 8];
        const ulonglong2* wp = (const ulonglong2*)&S[2 * 64 + kg * 8];
        ulonglong2 rA = rp[0], rB = rp[1];
        ulonglong2 kA = kp[0], kB = kp[1];
        ulonglong2 wA = wp[0], wB = wp[1];
        unsigned long long r2[4] = { rA.x, rA.y, rB.x, rB.y };
        unsigned long long k2[4] = { kA.x, kA.y, kB.x, kB.y };
        unsigned long long w2[4] = { wA.x, wA.y, wB.x, wB.y };

        unsigned long long ps2 = 0ULL;
        #pragma unroll
        for (int j2 = 0; j2 < 4; j2++) {
            if (reset) s2[j2] = 0ULL;
            unsigned long long kv2;
            asm("mul.rn.f32x2 %0, %1, %2;"     : "=l"(kv2)    : "l"(k2[j2]), "l"(vv2));
            asm("fma.rn.f32x2 %0, %1, %2, %3;" : "=l"(s2[j2]) : "l"(s2[j2]), "l"(w2[j2]), "l"(kv2));
            asm("fma.rn.f32x2 %0, %1, %2, %0;" : "+l"(ps2)    : "l"(r2[j2]), "l"(s2[j2]));
        }

        float plo = __uint_as_float((unsigned)(ps2 & 0xffffffffULL));
        float phi = __uint_as_float((unsigned)(ps2 >> 32));
        pbuf[t & 15][tid] = plo + phi;
        __syncthreads();

        if ((t & 7) == 7) {
            const int st = tid >> 6;
            const int vc = tid & 63;
            const int slot = (t - 7 + st) & 15;
            const float4* p4 = (const float4*)&pbuf[slot][vc * 8];
            float4 x0 = p4[0], x1 = p4[1];
            float o = ((x0.x + x0.y) + (x0.z + x0.w)) + ((x1.x + x1.y) + (x1.z + x1.w));
            o *= gbuf[slot][vc];
            const int trow = t - 7 + st;
            __nv_bfloat16 hi = __float2bfloat16(o);
            __nv_bfloat16 lo = __float2bfloat16(o - __bfloat162float(hi));
            size_t base = (size_t)trow * K3_;
            int c = h * 64 + vc;
            out_split[base + c]          = hi;
            out_split[base + C_ + c]     = hi;
            out_split[base + 2 * C_ + c] = lo;
        }
    }

    #pragma unroll
    for (int j2 = 0; j2 < 4; j2++) {
        float slo = __uint_as_float((unsigned)(s2[j2] & 0xffffffffULL));
        float shi = __uint_as_float((unsigned)(s2[j2] >> 32));
        g_sfin[h * 4096 + (kg * 8 + 2 * j2) * 64 + vcol]     = slo;
        g_sfin[h * 4096 + (kg * 8 + 2 * j2 + 1) * 64 + vcol] = shi;
    }
}

// ---------------- new_state writer ----------------
__global__ void k_state(float* __restrict__ dout, const float* __restrict__ x,
                        const int* __restrict__ lenp)
{
    int idx = blockIdx.x * blockDim.x + threadIdx.x;
    int L = lenp ? lenp[0] : T_;
    if (idx < C_)
        dout[(size_t)T_ * C_ + idx] = x[(size_t)(L - 1) * C_ + idx];
    if (idx < H_ * S_ * S_)
        dout[(size_t)T_ * C_ + C_ + idx] = g_sfin[idx];
}

// ---------------- host-side orchestration ----------------
template <typename Sym>
static void* devaddr_v(Sym& sym) {
    void* p = nullptr;
    cudaGetSymbolAddress(&p, sym);
    return p;
}

#define HG_SMEM (3 * 32768)

extern "C" void kernel_launch(void* const* d_in, const int* in_sizes, int n_in,
                              void* d_out, int out_size)
{
    int i = 0;
    const float* x       = (const float*)d_in[i++];
    const float* state   = (const float*)d_in[i++];
    const unsigned char* ns = (const unsigned char*)d_in[i++];
    const int* lenp = nullptr;
    if (n_in >= 20) { lenp = (const int*)d_in[i++]; }
    const float* maa_x = (const float*)d_in[i++];
    const float* maa_r = (const float*)d_in[i++];
    const float* maa_k = (const float*)d_in[i++];
    const float* maa_v = (const float*)d_in[i++];
    const float* maa_w = (const float*)d_in[i++];
    const float* maa_g = (const float*)d_in[i++];
    const float* maa_w1 = (const float*)d_in[i++];  // [C, 160]
    const float* maa_w2 = (const float*)d_in[i++];  // [5, 32, C]
    const float* tdecay = (const float*)d_in[i++];  // [C]
    const float* dec_w1 = (const float*)d_in[i++];  // [C, 64]
    const float* dec_w2 = (const float*)d_in[i++];  // [64, C]
    const float* Wq = (const float*)d_in[i++];      // [C, C]
    const float* Wk = (const float*)d_in[i++];      // [C, 512]
    const float* Wv = (const float*)d_in[i++];      // [C, 512]
    const float* Wg = (const float*)d_in[i++];      // [C, C]
    const float* Wo = (const float*)d_in[i++];      // [C, C]
    float* dout = (float*)d_out;

    float* p_sx   = (float*)devaddr_v(g_sx);
    float* p_t1   = (float*)devaddr_v(g_t1);
    float* p_t2   = (float*)devaddr_v(g_t2);
    float* p_r    = (float*)devaddr_v(g_r);
    float* p_k    = (float*)devaddr_v(g_k);
    float* p_v    = (float*)devaddr_v(g_v);
    float* p_ew   = (float*)devaddr_v(g_ew);
    float* p_gate = (float*)devaddr_v(g_gate);
    float* p_part = (float*)devaddr_v(g_part);
    __nv_bfloat16* p_ba_xxx = (__nv_bfloat16*)devaddr_v(g_ba_xxx);
    __nv_bfloat16* p_ba_r   = (__nv_bfloat16*)devaddr_v(g_ba_r);
    __nv_bfloat16* p_ba_k   = (__nv_bfloat16*)devaddr_v(g_ba_k);
    __nv_bfloat16* p_ba_v   = (__nv_bfloat16*)devaddr_v(g_ba_v);
    __nv_bfloat16* p_ba_w   = (__nv_bfloat16*)devaddr_v(g_ba_w);
    __nv_bfloat16* p_ba_g   = (__nv_bfloat16*)devaddr_v(g_ba_g);
    __nv_bfloat16* p_bwA  = (__nv_bfloat16*)devaddr_v(g_bwA);
    __nv_bfloat16* p_bwB  = (__nv_bfloat16*)devaddr_v(g_bwB);
    __nv_bfloat16* p_bwC  = (__nv_bfloat16*)devaddr_v(g_bwC);
    __nv_bfloat16* p_bw1  = (__nv_bfloat16*)devaddr_v(g_bw1);
    __nv_bfloat16* p_bw2  = (__nv_bfloat16*)devaddr_v(g_bw2);
    __nv_bfloat16* p_bws1 = (__nv_bfloat16*)devaddr_v(g_bws1);
    __nv_bfloat16* p_bws2 = (__nv_bfloat16*)devaddr_v(g_bws2);

    cudaFuncSetAttribute(hgemm, cudaFuncAttributeMaxDynamicSharedMemorySize, HG_SMEM);

    const int EW = 256;
    const int GE = (T_ * C_ + EW - 1) / EW;
    dim3 blk(256);
    dim3 cw(32, 8);

    // 0) ALL weight conversions in one launch (launch index 0)
    {
        CB cb = {};
        cb.src[0] = Wq;     cb.dst[0] = p_bwA;  cb.N[0] = C_;        cb.xt[0] = 64;
        cb.src[1] = Wg;     cb.dst[1] = p_bwB;  cb.N[1] = C_;        cb.xt[1] = 64;
        cb.src[2] = Wo;     cb.dst[2] = p_bwC;  cb.N[2] = C_;        cb.xt[2] = 64;
        cb.src[3] = Wk;     cb.dst[3] = p_bw1;  cb.N[3] = 512;       cb.xt[3] = 16;
        cb.src[4] = Wv;     cb.dst[4] = p_bw2;  cb.N[4] = 512;       cb.xt[4] = 16;
        cb.src[5] = maa_w1; cb.dst[5] = p_bws1; cb.N[5] = 5 * LMAA_; cb.xt[5] = 8;
        cb.src[6] = dec_w1; cb.dst[6] = p_bws2; cb.N[6] = LDEC_;     cb.xt[6] = 8;
        k_conv_all<<<dim3(240, 64), cw>>>(cb);
    }

    // 1) token shift -> sx (f32) + ba_xxx (bf16 split)       (launch 1)
    k_shift<<<GE, EW>>>(x, state, ns, maa_x);

    // 2) t1 = tanh(xxx @ maa_w1) [T,160]: split-K 4 + reduce (launches 2,3)
    {
        TB tb = {};
        tb.A[0] = p_ba_xxx; tb.B[0] = p_bws1; tb.Cc[0] = p_part;
        tb.N[0] = 5 * LMAA_; tb.ldc[0] = 5 * LMAA_; tb.epi[0] = EPI_NONE;
        hgemm<<<dim3(2, 16, SPLITK), blk, HG_SMEM>>>(tb, 96 / SPLITK, T_ * 5 * LMAA_);
        int n = T_ * 5 * LMAA_;
        k_red_tanh<<<(n + EW - 1) / EW, EW>>>(p_part, p_t1, n, n);
    }

    // 3) MIX (FFMA2, K=32): writes 5 bf16-split activation buffers (launch 4)
    {
        Batch bt = {};
        const float* vecs[5] = { maa_r, maa_k, maa_v, maa_w, maa_g };
        void* outs[5] = { p_ba_r, p_ba_k, p_ba_v, p_ba_w, p_ba_g };
        for (int z = 0; z < 5; z++) {
            bt.A[z]  = p_t1 + z * LMAA_;
            bt.B[z]  = maa_w2 + (size_t)z * LMAA_ * C_;
            bt.Cc[z] = outs[z];
            bt.vec[z] = vecs[z];
        }
        gemm128<EPI_MIX><<<dim3(C_ / 128, T_ / 128, 5), blk>>>(bt, 5 * LMAA_, C_, C_, C_, LMAA_, x, p_sx);
    }

    // 4) r + gate + k + v in ONE launch (z=4)  (launch 5 — ncu -s 5 profiles THIS)
    {
        TB tb = {};
        tb.A[0] = p_ba_r; tb.B[0] = p_bwA; tb.Cc[0] = p_r;    tb.N[0] = C_;  tb.ldc[0] = C_;  tb.epi[0] = EPI_NONE;
        tb.A[1] = p_ba_g; tb.B[1] = p_bwB; tb.Cc[1] = p_gate; tb.N[1] = C_;  tb.ldc[1] = C_;  tb.epi[1] = EPI_SIG;
        tb.A[2] = p_ba_k; tb.B[2] = p_bw1; tb.Cc[2] = p_k;    tb.N[2] = 512; tb.ldc[2] = 512; tb.epi[2] = EPI_NONE;
        tb.A[3] = p_ba_v; tb.B[3] = p_bw2; tb.Cc[3] = p_v;    tb.N[3] = 512; tb.ldc[3] = 512; tb.epi[3] = EPI_NONE;
        hgemm<<<dim3(16, 16, 4), blk, HG_SMEM>>>(tb, 96, 0);
    }

    // 5) t2 = tanh(xw @ dec_w1) [T,64]: split-K 4 + reduce
    {
        TB tb = {};
        tb.A[0] = p_ba_w; tb.B[0] = p_bws2; tb.Cc[0] = p_part;
        tb.N[0] = LDEC_; tb.ldc[0] = LDEC_; tb.epi[0] = EPI_NONE;
        hgemm<<<dim3(1, 16, SPLITK), blk, HG_SMEM>>>(tb, 96 / SPLITK, T_ * LDEC_);
        int n = T_ * LDEC_;
        k_red_tanh<<<(n + EW - 1) / EW, EW>>>(p_part, p_t2, n, n);
    }

    // 6) ew = exp(max(-exp(t2@dec_w2 + tdecay), -5)) (FFMA2, K=64)
    {
        Batch bt = {};
        bt.A[0] = p_t2; bt.B[0] = dec_w2; bt.Cc[0] = p_ew; bt.vec[0] = tdecay;
        gemm128<EPI_DECAY><<<dim3(C_ / 128, T_ / 128, 1), blk>>>(bt, LDEC_, C_, C_, C_, LDEC_, nullptr, nullptr);
    }

    // 7) scan: writes gated output as bf16 split into ba_r (reused)
    k_scan<<<H_, 512>>>(state, ns, p_ba_r);

    // 8) final projection: dout = (out*gate) @ Wo
    {
        TB tb = {};
        tb.A[0] = p_ba_r; tb.B[0] = p_bwC; tb.Cc[0] = dout;
        tb.N[0] = C_; tb.ldc[0] = C_; tb.epi[0] = EPI_NONE;
        hgemm<<<dim3(16, 16, 1), blk, HG_SMEM>>>(tb, 96, 0);
    }

    // 9) new_state (only if the harness expects both outputs)
    if (out_size >= T_ * C_ + (S_ + 1) * C_) {
        int n = H_ * S_ * S_;
        k_state<<<(n + EW - 1) / EW, EW>>>(dout, x, lenp);
    }
}

// round 14
// speedup vs baseline: 1.4575x; 1.3032x over previous
#include <cuda_runtime.h>
#include <cuda_bf16.h>
#include <math.h>
#include <stdint.h>

#define T_ 2048
#define C_ 2048
#define H_ 32
#define S_ 64
#define HKV_ 8
#define LMAA_ 32
#define LDEC_ 64
#define K3_ (3 * C_)   // 6144
#define SPLITK 4

// ---------------- f32 scratch ----------------
__device__ float g_sx [T_*C_];
__device__ float g_t1 [T_*5*LMAA_];
__device__ float g_t2 [T_*LDEC_];
__device__ float g_r  [T_*C_];
__device__ float g_k  [T_*HKV_*S_];
__device__ float g_v  [T_*HKV_*S_];
__device__ float g_ew [T_*C_];
__device__ float g_keff[T_*C_];
__device__ float g_gate[T_*C_];
__device__ float g_sfin[H_*S_*S_];
__device__ float g_part[SPLITK * T_ * (5*LMAA_ + LDEC_)];

// ---------------- bf16 3-split buffers (A'=[hi|hi|lo], W'=[hi|lo|hi]) ----------------
__device__ __align__(128) __nv_bfloat16 g_ba_xxx[(size_t)T_ * K3_];
__device__ __align__(128) __nv_bfloat16 g_ba_r  [(size_t)T_ * K3_];   // xr, later reused for out
__device__ __align__(128) __nv_bfloat16 g_ba_k  [(size_t)T_ * K3_];
__device__ __align__(128) __nv_bfloat16 g_ba_v  [(size_t)T_ * K3_];
__device__ __align__(128) __nv_bfloat16 g_ba_w  [(size_t)T_ * K3_];
__device__ __align__(128) __nv_bfloat16 g_ba_g  [(size_t)T_ * K3_];
__device__ __align__(128) __nv_bfloat16 g_bwA[(size_t)2048 * K3_];    // Wq
__device__ __align__(128) __nv_bfloat16 g_bwB[(size_t)2048 * K3_];    // Wg
__device__ __align__(128) __nv_bfloat16 g_bwC[(size_t)2048 * K3_];    // Wo
__device__ __align__(128) __nv_bfloat16 g_bw1[(size_t)512 * K3_];     // Wk
__device__ __align__(128) __nv_bfloat16 g_bw2[(size_t)512 * K3_];     // Wv
__device__ __align__(128) __nv_bfloat16 g_bws1[(size_t)256 * K3_];    // maa_w1 (160->256)
__device__ __align__(128) __nv_bfloat16 g_bws2[(size_t)256 * K3_];    // dec_w1 (64->256)

// ---------------- epilogue ids ----------------
#define EPI_NONE  0
#define EPI_TANH  1
#define EPI_SIG   2
#define EPI_MIX   3
#define EPI_DECAY 4

// ---------------- mma.sync helpers ----------------
__device__ __forceinline__ uint32_t smem_u32(const void* p) {
    uint32_t a;
    asm("{ .reg .u64 t; cvta.to.shared.u64 t, %1; cvt.u32.u64 %0, t; }" : "=r"(a) : "l"(p));
    return a;
}
__device__ __forceinline__ void cp_async16(uint32_t saddr, const void* g) {
    asm volatile("cp.async.cg.shared.global [%0], [%1], 16;" :: "r"(saddr), "l"(g) : "memory");
}
__device__ __forceinline__ void cp_async4(uint32_t saddr, const void* g) {
    asm volatile("cp.async.ca.shared.global [%0], [%1], 4;" :: "r"(saddr), "l"(g) : "memory");
}
__device__ __forceinline__ void ldmatrix_x4(uint32_t* r, uint32_t addr) {
    asm volatile("ldmatrix.sync.aligned.m8n8.x4.shared.b16 {%0,%1,%2,%3}, [%4];"
        : "=r"(r[0]), "=r"(r[1]), "=r"(r[2]), "=r"(r[3]) : "r"(addr));
}
__device__ __forceinline__ void mma16816(float* c, const uint32_t* a, uint32_t b0, uint32_t b1) {
    asm volatile("mma.sync.aligned.m16n8k16.row.col.f32.bf16.bf16.f32 "
        "{%0,%1,%2,%3}, {%4,%5,%6,%7}, {%8,%9}, {%0,%1,%2,%3};"
        : "+f"(c[0]), "+f"(c[1]), "+f"(c[2]), "+f"(c[3])
        : "r"(a[0]), "r"(a[1]), "r"(a[2]), "r"(a[3]), "r"(b0), "r"(b1));
}

struct TB {
    const __nv_bfloat16* A[8];
    const __nv_bfloat16* B[8];
    float*               Cc[8];
    int N[8];
    int ldc[8];
    int epi[8];
    int nch[8];   // K chunks (of 64)
    int kc0[8];   // start chunk (split-K)
};

// ---------------- HMMA bf16 GEMM: C = A'[M,K'] @ B'[N,K']^T ----------------
// 128x128 CTA tile, 8 warps (2m x 4n), warp 64x32 m16n8k16, BK=64, 3-stage cp.async.
// Per-z N/ldc/epi/nch/kc0 — heterogeneous batch in one launch.
__global__ __launch_bounds__(256, 2)
void hgemm(TB bt)
{
    const int z = blockIdx.z;
    const __nv_bfloat16* __restrict__ Ag = bt.A[z];
    const __nv_bfloat16* __restrict__ Bg = bt.B[z];
    float* __restrict__ Cg = bt.Cc[z];
    const int N = bt.N[z], ldc = bt.ldc[z], epi = bt.epi[z];
    const int nch = bt.nch[z], kc0 = bt.kc0[z];
    if (blockIdx.x * 128 >= N) return;

    extern __shared__ char smem[];
    const uint32_t sbase = smem_u32(smem);   // 3 stages x (A 16KB | B 16KB)

    const int tid  = threadIdx.x;
    const int lane = tid & 31;
    const int wid  = tid >> 5;
    const int wm   = wid >> 2;    // 0..1
    const int wn   = wid & 3;     // 0..3
    const int bx = blockIdx.x, by = blockIdx.y;

    float acc[4][4][4];
    #pragma unroll
    for (int i = 0; i < 4; i++)
        #pragma unroll
        for (int j = 0; j < 4; j++)
            #pragma unroll
            for (int k = 0; k < 4; k++) acc[i][j][k] = 0.f;

    const __nv_bfloat16* Abase = Ag + (size_t)(by * 128) * K3_;
    const __nv_bfloat16* Bbase = Bg + (size_t)(bx * 128) * K3_;

    auto load_stage = [&](int kt, int s) {
        const uint32_t sa = sbase + s * 32768;
        const __nv_bfloat16* Agk = Abase + (size_t)(kc0 + kt) * 64;
        const __nv_bfloat16* Bgk = Bbase + (size_t)(kc0 + kt) * 64;
        #pragma unroll
        for (int q = 0; q < 4; q++) {
            const int c = q * 256 + tid;
            const int row = c >> 3, j = c & 7;
            uint32_t off = (uint32_t)(row * 128 + j * 16);
            off ^= (off >> 3) & 0x70;
            cp_async16(sa + off,         Agk + (size_t)row * K3_ + j * 8);
            cp_async16(sa + 16384 + off, Bgk + (size_t)row * K3_ + j * 8);
        }
        asm volatile("cp.async.commit_group;" ::: "memory");
    };

    const int a_roff = (wm * 64 + (lane & 15)) * 128 + (lane >> 4) * 16;
    const int b_roff = (wn * 32 + (lane & 7) + ((lane >> 4) << 3)) * 128 + ((lane >> 3) & 1) * 16;

    auto compute = [&](int s) {
        const uint32_t sa = sbase + s * 32768;
        const uint32_t sbb = sa + 16384;
        #pragma unroll
        for (int ks = 0; ks < 4; ks++) {
            uint32_t bf2[2][4];
            #pragma unroll
            for (int nt2 = 0; nt2 < 2; nt2++) {
                uint32_t off = (uint32_t)(b_roff + nt2 * 16 * 128 + ks * 32);
                off ^= (off >> 3) & 0x70;
                ldmatrix_x4(bf2[nt2], sbb + off);
            }
            uint32_t af[4][4];
            #pragma unroll
            for (int mt = 0; mt < 4; mt++) {
                uint32_t off = (uint32_t)(a_roff + mt * 16 * 128 + ks * 32);
                off ^= (off >> 3) & 0x70;
                ldmatrix_x4(af[mt], sa + off);
            }
            #pragma unroll
            for (int mt = 0; mt < 4; mt++)
                #pragma unroll
                for (int nt = 0; nt < 4; nt++)
                    mma16816(acc[mt][nt], af[mt],
                             bf2[nt >> 1][(nt & 1) * 2], bf2[nt >> 1][(nt & 1) * 2 + 1]);
        }
    };

    load_stage(0, 0);
    load_stage(1, 1);

    for (int kt = 0; kt < nch; kt++) {
        asm volatile("cp.async.wait_group 1;" ::: "memory");
        __syncthreads();
        if (kt + 2 < nch) load_stage(kt + 2, (kt + 2) % 3);
        else asm volatile("cp.async.commit_group;" ::: "memory");
        compute(kt % 3);
    }

    // epilogue (runtime epi: NONE / TANH / SIG)
    #pragma unroll
    for (int mt = 0; mt < 4; mt++) {
        #pragma unroll
        for (int hrow = 0; hrow < 2; hrow++) {
            const int row = by * 128 + wm * 64 + mt * 16 + hrow * 8 + (lane >> 2);
            float* crow = Cg + (size_t)row * ldc;
            #pragma unroll
            for (int nt = 0; nt < 4; nt++) {
                const int col = bx * 128 + wn * 32 + nt * 8 + (lane & 3) * 2;
                if (col >= N) continue;
                float v0 = acc[mt][nt][hrow * 2 + 0];
                float v1 = acc[mt][nt][hrow * 2 + 1];
                if (epi == EPI_TANH) { v0 = tanhf(v0); v1 = tanhf(v1); }
                else if (epi == EPI_SIG) { v0 = 1.f/(1.f+expf(-v0)); v1 = 1.f/(1.f+expf(-v1)); }
                *(float2*)&crow[col] = make_float2(v0, v1);
            }
        }
    }
}

// ---------------- split-K reducer + tanh ----------------
__global__ void k_red_tanh(const float* __restrict__ part, float* __restrict__ out,
                           int n, int stride)
{
    int i = blockIdx.x * blockDim.x + threadIdx.x;
    if (i >= n) return;
    float s = part[i] + part[(size_t)stride + i]
            + part[(size_t)2 * stride + i] + part[(size_t)3 * stride + i];
    out[i] = tanhf(s);
}

// ---------------- batched weight conversion (ALL weights, one launch) ----------------
struct CB {
    const float*   src[7];
    __nv_bfloat16* dst[7];
    int            N[7];
    int            xt[7];
};

__global__ void k_conv_all(CB cb)
{
    __shared__ float tile[32][33];
    int bx = blockIdx.x;
    int w = 0;
    while (bx >= cb.xt[w]) { bx -= cb.xt[w]; w++; }
    const float* __restrict__ src = cb.src[w];
    __nv_bfloat16* __restrict__ dst = cb.dst[w];
    const int N = cb.N[w];

    const int n0 = bx * 32;
    const int k0 = blockIdx.y * 32;
    const int tx = threadIdx.x, ty = threadIdx.y;  // (32, 8)
    #pragma unroll
    for (int yy = 0; yy < 32; yy += 8) {
        int n = n0 + tx, k = k0 + ty + yy;
        tile[ty + yy][tx] = (n < N) ? src[(size_t)k * N + n] : 0.f;
    }
    __syncthreads();
    #pragma unroll
    for (int yy = 0; yy < 32; yy += 8) {
        int n = n0 + ty + yy;
        int k = k0 + tx;
        float a = tile[tx][ty + yy];
        __nv_bfloat16 hi = __float2bfloat16(a);
        __nv_bfloat16 lo = __float2bfloat16(a - __bfloat162float(hi));
        size_t base = (size_t)n * K3_;
        dst[base + k] = hi;
        dst[base + C_ + k] = lo;
        dst[base + 2 * C_ + k] = hi;
    }
}

// ---------------- FFMA2 GEMM (MIX K=32 -> bf16 split out, DECAY K=64 -> ew + keff) ----
struct Batch {
    const float* A[8];
    const float* B[8];
    void*        Cc[8];
    const float* vec[8];
};

template<int EPI>
__global__ __launch_bounds__(256, 2)
void gemm128(Batch bt, int lda, int ldb, int ldc, int N, int K,
             const float* __restrict__ aux1, const float* __restrict__ aux2)
{
    __shared__ float2 As[2][16][128];
    __shared__ float  Bs[2][16][128];

    const int z = blockIdx.z;
    const float* __restrict__ A   = bt.A[z];
    const float* __restrict__ B   = bt.B[z];
    const float* __restrict__ vec = bt.vec[z];

    const int tid = threadIdx.x;
    const int bx = blockIdx.x, by = blockIdx.y;
    const int arow = tid >> 1,  acol = (tid & 1) * 8;
    const int brow = tid >> 4,  bcol = (tid & 15) * 8;
    const int tx = tid & 15,    ty = tid >> 4;

    unsigned long long acc[8][4];
    #pragma unroll
    for (int i = 0; i < 8; i++)
        #pragma unroll
        for (int j = 0; j < 4; j++) acc[i][j] = 0ULL;

    const float* Ap = A + (size_t)(by * 128 + arow) * lda + acol;
    const int gcolb = bx * 128 + bcol;

    float4 a0, a1, b0, b1;
    auto loadAB = [&](int k0) {
        a0 = *(const float4*)(Ap + k0);
        a1 = *(const float4*)(Ap + k0 + 4);
        const float* bp = B + (size_t)(k0 + brow) * ldb + gcolb;
        b0 = *(const float4*)bp;
        b1 = *(const float4*)(bp + 4);
    };
    auto storeAB = [&](int buf) {
        As[buf][acol + 0][arow] = make_float2(a0.x, a0.x);
        As[buf][acol + 1][arow] = make_float2(a0.y, a0.y);
        As[buf][acol + 2][arow] = make_float2(a0.z, a0.z);
        As[buf][acol + 3][arow] = make_float2(a0.w, a0.w);
        As[buf][acol + 4][arow] = make_float2(a1.x, a1.x);
        As[buf][acol + 5][arow] = make_float2(a1.y, a1.y);
        As[buf][acol + 6][arow] = make_float2(a1.z, a1.z);
        As[buf][acol + 7][arow] = make_float2(a1.w, a1.w);
        *(float4*)&Bs[buf][brow][bcol]     = b0;
        *(float4*)&Bs[buf][brow][bcol + 4] = b1;
    };

    loadAB(0);
    storeAB(0);
    __syncthreads();

    const int nt = K >> 4;
    for (int kt = 0; kt < nt; kt++) {
        const int cur = kt & 1;
        if (kt + 1 < nt) loadAB((kt + 1) << 4);

        #pragma unroll
        for (int kk = 0; kk < 16; kk++) {
            unsigned long long a2[8], b2[4];
            const ulonglong2* ap = (const ulonglong2*)&As[cur][kk][ty * 8];
            ulonglong2 w;
            w = ap[0]; a2[0] = w.x; a2[1] = w.y;
            w = ap[1]; a2[2] = w.x; a2[3] = w.y;
            w = ap[2]; a2[4] = w.x; a2[5] = w.y;
            w = ap[3]; a2[6] = w.x; a2[7] = w.y;
            const ulonglong2* bp2 = (const ulonglong2*)&Bs[cur][kk][tx * 8];
            w = bp2[0]; b2[0] = w.x; b2[1] = w.y;
            w = bp2[1]; b2[2] = w.x; b2[3] = w.y;
            #pragma unroll
            for (int i = 0; i < 8; i++)
                #pragma unroll
                for (int j = 0; j < 4; j++)
                    asm("fma.rn.f32x2 %0, %1, %2, %0;"
                        : "+l"(acc[i][j]) : "l"(a2[i]), "l"(b2[j]));
        }

        if (kt + 1 < nt) storeAB(cur ^ 1);
        __syncthreads();
    }

    #pragma unroll
    for (int i = 0; i < 8; i++) {
        const int row = by * 128 + ty * 8 + i;
        #pragma unroll
        for (int j = 0; j < 4; j++) {
            const int col = bx * 128 + tx * 8 + 2 * j;
            float v0 = __uint_as_float((unsigned)(acc[i][j] & 0xffffffffULL));
            float v1 = __uint_as_float((unsigned)(acc[i][j] >> 32));
            if (EPI == EPI_MIX) {
                size_t idx = (size_t)row * C_ + col;
                v0 = aux1[idx]     + aux2[idx]     * (vec[col]     + v0);
                v1 = aux1[idx + 1] + aux2[idx + 1] * (vec[col + 1] + v1);
                __nv_bfloat16 h0 = __float2bfloat16(v0);
                __nv_bfloat16 h1 = __float2bfloat16(v1);
                __nv_bfloat16 l0 = __float2bfloat16(v0 - __bfloat162float(h0));
                __nv_bfloat16 l1 = __float2bfloat16(v1 - __bfloat162float(h1));
                __nv_bfloat162 hh; hh.x = h0; hh.y = h1;
                __nv_bfloat162 ll; ll.x = l0; ll.y = l1;
                __nv_bfloat16* bout = (__nv_bfloat16*)bt.Cc[z];
                size_t base = (size_t)row * K3_;
                *(__nv_bfloat162*)&bout[base + col]          = hh;
                *(__nv_bfloat162*)&bout[base + C_ + col]     = hh;
                *(__nv_bfloat162*)&bout[base + 2 * C_ + col] = ll;
            } else {  // EPI_DECAY: write ew AND keff = k*(1-ew)
                float* crow = (float*)bt.Cc[z] + (size_t)row * ldc;
                float lw0 = fmaxf(-expf(v0 + vec[col]), -5.0f);
                float lw1 = fmaxf(-expf(v1 + vec[col + 1]), -5.0f);
                float e0 = expf(lw0), e1 = expf(lw1);
                *(float2*)&crow[col] = make_float2(e0, e1);
                int hh2 = col >> 6, ss = col & 63;
                float2 kv = *(const float2*)&g_k[(size_t)row * 512 + (hh2 >> 2) * 64 + ss];
                *(float2*)&g_keff[(size_t)row * C_ + col] =
                    make_float2(kv.x * (1.f - e0), kv.y * (1.f - e1));
            }
        }
    }
}

// ---------------- token shift: writes sx (f32) + xxx (bf16 split) ----------------
__global__ void k_shift(const float* __restrict__ x, const float* __restrict__ state,
                        const unsigned char* __restrict__ ns,
                        const float* __restrict__ maa_x)
{
    int idx = blockIdx.x * blockDim.x + threadIdx.x;
    if (idx >= T_ * C_) return;
    int t = idx >> 11;
    int c = idx & 2047;
    float prev = (t == 0) ? state[c] : x[idx - C_];
    if (ns[t]) prev = 0.f;
    float s = prev - x[idx];
    g_sx[idx] = s;
    float v = x[idx] + s * maa_x[c];
    __nv_bfloat16 hi = __float2bfloat16(v);
    __nv_bfloat16 lo = __float2bfloat16(v - __bfloat162float(hi));
    size_t base = (size_t)t * K3_;
    g_ba_xxx[base + c]          = hi;
    g_ba_xxx[base + C_ + c]     = hi;
    g_ba_xxx[base + 2 * C_ + c] = lo;
}

// ---------------- RWKV scan v3: cp.async ring, 2 barriers per 8 steps ----------------
// 512 threads: vcol = tid>>3, kg = tid&7. 320 loader threads (a<5) cp.async one f32
// per array per step into a 32-slot smem ring, 16 steps ahead. Superstep = 8 steps:
// issue+commit, wait_group 2, bar, 8 state updates (pbuf), bar, batched reduce+store.
#define SCAN_SLOT 320                          // floats per slot: r|keff|ew|v|gate
#define SCAN_SMEM (32*SCAN_SLOT*4 + 8*512*4 + T_)

__global__ __launch_bounds__(512)
void k_scan(const float* __restrict__ state, const unsigned char* __restrict__ ns,
            __nv_bfloat16* __restrict__ out_split)
{
    extern __shared__ char sm[];
    float* ring = (float*)sm;                                   // [32][320]
    float* pbuf = (float*)(sm + 32 * SCAN_SLOT * 4);            // [8][512]
    unsigned char* nsh = (unsigned char*)(sm + 32 * SCAN_SLOT * 4 + 8 * 512 * 4);

    const int h = blockIdx.x;
    const int tid = threadIdx.x;
    const int vcol = tid >> 3;
    const int kg = tid & 7;

    unsigned long long s2[4];
    #pragma unroll
    for (int j2 = 0; j2 < 4; j2++) {
        float slo = state[C_ + h * 4096 + (kg * 8 + 2 * j2) * 64 + vcol];
        float shi = state[C_ + h * 4096 + (kg * 8 + 2 * j2 + 1) * 64 + vcol];
        asm("mov.b64 %0, {%1, %2};" : "=l"(s2[j2]) : "f"(slo), "f"(shi));
    }

    for (int i = tid; i < T_; i += 512) nsh[i] = ns[i];

    const int a  = tid >> 6;
    const int li = tid & 63;
    const bool loader = (a < 5);
    const float* src = nullptr;
    int stride = C_;
    if (a == 0)      src = g_r    + (size_t)h * 64 + li;
    else if (a == 1) src = g_keff + (size_t)h * 64 + li;
    else if (a == 2) src = g_ew   + (size_t)h * 64 + li;
    else if (a == 3) { src = g_v + (size_t)(h >> 2) * 64 + li; stride = 512; }
    else if (a == 4) src = g_gate + (size_t)h * 64 + li;

    const uint32_t sring = smem_u32(ring);
    const uint32_t dbase = (uint32_t)(a * 64 + li) * 4;

    auto issue8 = [&](int tbase) {
        if (loader) {
            #pragma unroll
            for (int p = 0; p < 8; p++) {
                int t = tbase + p;
                cp_async4(sring + (uint32_t)((t & 31) * SCAN_SLOT) * 4 + dbase,
                          src + (size_t)t * stride);
            }
        }
        asm volatile("cp.async.commit_group;" ::: "memory");
    };

    // prologue: steps 0..7 and 8..15 (2 groups)
    issue8(0);
    issue8(8);

    for (int S = 0; S < T_ / 8; S++) {
        const int t0 = S * 8;
        if (t0 + 16 < T_) issue8(t0 + 16);
        else asm volatile("cp.async.commit_group;" ::: "memory");
        asm volatile("cp.async.wait_group 2;" ::: "memory");
        __syncthreads();

        #pragma unroll
        for (int p = 0; p < 8; p++) {
            const int t = t0 + p;
            const float* Sl = ring + (t & 31) * SCAN_SLOT;

            float vv = Sl[3 * 64 + vcol];
            unsigned long long vv2;
            asm("mov.b64 %0, {%1, %1};" : "=l"(vv2) : "f"(vv));

            const bool reset = (nsh[t] != 0);

            const ulonglong2* rp = (const ulonglong2*)&Sl[0 * 64 + kg * 8];
            const ulonglong2* kp = (const ulonglong2*)&Sl[1 * 64 + kg * 8];
            const ulonglong2* wp = (const ulonglong2*)&Sl[2 * 64 + kg * 8];
            ulonglong2 rA = rp[0], rB = rp[1];
            ulonglong2 kA = kp[0], kB = kp[1];
            ulonglong2 wA = wp[0], wB = wp[1];
            unsigned long long r2[4] = { rA.x, rA.y, rB.x, rB.y };
            unsigned long long k2[4] = { kA.x, kA.y, kB.x, kB.y };
            unsigned long long w2[4] = { wA.x, wA.y, wB.x, wB.y };

            unsigned long long ps2 = 0ULL;
            #pragma unroll
            for (int j2 = 0; j2 < 4; j2++) {
                if (reset) s2[j2] = 0ULL;
                unsigned long long kv2;
                asm("mul.rn.f32x2 %0, %1, %2;"     : "=l"(kv2)    : "l"(k2[j2]), "l"(vv2));
                asm("fma.rn.f32x2 %0, %1, %2, %3;" : "=l"(s2[j2]) : "l"(s2[j2]), "l"(w2[j2]), "l"(kv2));
                asm("fma.rn.f32x2 %0, %1, %2, %0;" : "+l"(ps2)    : "l"(r2[j2]), "l"(s2[j2]));
            }

            float plo = __uint_as_float((unsigned)(ps2 & 0xffffffffULL));
            float phi = __uint_as_float((unsigned)(ps2 >> 32));
            pbuf[p * 512 + tid] = plo + phi;
        }
        __syncthreads();

        // batched reduce for steps t0..t0+7: thread -> (st, vc)
        {
            const int st = tid >> 6;       // 0..7
            const int vc = tid & 63;
            const float4* p4 = (const float4*)&pbuf[st * 512 + vc * 8];
            float4 x0 = p4[0], x1 = p4[1];
            float o = ((x0.x + x0.y) + (x0.z + x0.w)) + ((x1.x + x1.y) + (x1.z + x1.w));
            const int t = t0 + st;
            o *= ring[(t & 31) * SCAN_SLOT + 4 * 64 + vc];
            __nv_bfloat16 hi = __float2bfloat16(o);
            __nv_bfloat16 lo = __float2bfloat16(o - __bfloat162float(hi));
            size_t base = (size_t)t * K3_;
            int c = h * 64 + vc;
            out_split[base + c]          = hi;
            out_split[base + C_ + c]     = hi;
            out_split[base + 2 * C_ + c] = lo;
        }
    }

    #pragma unroll
    for (int j2 = 0; j2 < 4; j2++) {
        float slo = __uint_as_float((unsigned)(s2[j2] & 0xffffffffULL));
        float shi = __uint_as_float((unsigned)(s2[j2] >> 32));
        g_sfin[h * 4096 + (kg * 8 + 2 * j2) * 64 + vcol]     = slo;
        g_sfin[h * 4096 + (kg * 8 + 2 * j2 + 1) * 64 + vcol] = shi;
    }
}

// ---------------- new_state writer ----------------
__global__ void k_state(float* __restrict__ dout, const float* __restrict__ x,
                        const int* __restrict__ lenp)
{
    int idx = blockIdx.x * blockDim.x + threadIdx.x;
    int L = lenp ? lenp[0] : T_;
    if (idx < C_)
        dout[(size_t)T_ * C_ + idx] = x[(size_t)(L - 1) * C_ + idx];
    if (idx < H_ * S_ * S_)
        dout[(size_t)T_ * C_ + C_ + idx] = g_sfin[idx];
}

// ---------------- host-side orchestration ----------------
template <typename Sym>
static void* devaddr_v(Sym& sym) {
    void* p = nullptr;
    cudaGetSymbolAddress(&p, sym);
    return p;
}

#define HG_SMEM (3 * 32768)

extern "C" void kernel_launch(void* const* d_in, const int* in_sizes, int n_in,
                              void* d_out, int out_size)
{
    int i = 0;
    const float* x       = (const float*)d_in[i++];
    const float* state   = (const float*)d_in[i++];
    const unsigned char* ns = (const unsigned char*)d_in[i++];
    const int* lenp = nullptr;
    if (n_in >= 20) { lenp = (const int*)d_in[i++]; }
    const float* maa_x = (const float*)d_in[i++];
    const float* maa_r = (const float*)d_in[i++];
    const float* maa_k = (const float*)d_in[i++];
    const float* maa_v = (const float*)d_in[i++];
    const float* maa_w = (const float*)d_in[i++];
    const float* maa_g = (const float*)d_in[i++];
    const float* maa_w1 = (const float*)d_in[i++];  // [C, 160]
    const float* maa_w2 = (const float*)d_in[i++];  // [5, 32, C]
    const float* tdecay = (const float*)d_in[i++];  // [C]
    const float* dec_w1 = (const float*)d_in[i++];  // [C, 64]
    const float* dec_w2 = (const float*)d_in[i++];  // [64, C]
    const float* Wq = (const float*)d_in[i++];      // [C, C]
    const float* Wk = (const float*)d_in[i++];      // [C, 512]
    const float* Wv = (const float*)d_in[i++];      // [C, 512]
    const float* Wg = (const float*)d_in[i++];      // [C, C]
    const float* Wo = (const float*)d_in[i++];      // [C, C]
    float* dout = (float*)d_out;

    float* p_sx   = (float*)devaddr_v(g_sx);
    float* p_t1   = (float*)devaddr_v(g_t1);
    float* p_t2   = (float*)devaddr_v(g_t2);
    float* p_r    = (float*)devaddr_v(g_r);
    float* p_k    = (float*)devaddr_v(g_k);
    float* p_v    = (float*)devaddr_v(g_v);
    float* p_ew   = (float*)devaddr_v(g_ew);
    float* p_gate = (float*)devaddr_v(g_gate);
    float* p_part = (float*)devaddr_v(g_part);
    __nv_bfloat16* p_ba_xxx = (__nv_bfloat16*)devaddr_v(g_ba_xxx);
    __nv_bfloat16* p_ba_r   = (__nv_bfloat16*)devaddr_v(g_ba_r);
    __nv_bfloat16* p_ba_k   = (__nv_bfloat16*)devaddr_v(g_ba_k);
    __nv_bfloat16* p_ba_v   = (__nv_bfloat16*)devaddr_v(g_ba_v);
    __nv_bfloat16* p_ba_w   = (__nv_bfloat16*)devaddr_v(g_ba_w);
    __nv_bfloat16* p_ba_g   = (__nv_bfloat16*)devaddr_v(g_ba_g);
    __nv_bfloat16* p_bwA  = (__nv_bfloat16*)devaddr_v(g_bwA);
    __nv_bfloat16* p_bwB  = (__nv_bfloat16*)devaddr_v(g_bwB);
    __nv_bfloat16* p_bwC  = (__nv_bfloat16*)devaddr_v(g_bwC);
    __nv_bfloat16* p_bw1  = (__nv_bfloat16*)devaddr_v(g_bw1);
    __nv_bfloat16* p_bw2  = (__nv_bfloat16*)devaddr_v(g_bw2);
    __nv_bfloat16* p_bws1 = (__nv_bfloat16*)devaddr_v(g_bws1);
    __nv_bfloat16* p_bws2 = (__nv_bfloat16*)devaddr_v(g_bws2);

    cudaFuncSetAttribute(hgemm, cudaFuncAttributeMaxDynamicSharedMemorySize, HG_SMEM);
    cudaFuncSetAttribute(k_scan, cudaFuncAttributeMaxDynamicSharedMemorySize, SCAN_SMEM);

    const int EW = 256;
    const int GE = (T_ * C_ + EW - 1) / EW;
    dim3 blk(256);
    dim3 cw(32, 8);

    // 0) ALL weight conversions in one launch
    {
        CB cb = {};
        cb.src[0] = Wq;     cb.dst[0] = p_bwA;  cb.N[0] = C_;        cb.xt[0] = 64;
        cb.src[1] = Wg;     cb.dst[1] = p_bwB;  cb.N[1] = C_;        cb.xt[1] = 64;
        cb.src[2] = Wo;     cb.dst[2] = p_bwC;  cb.N[2] = C_;        cb.xt[2] = 64;
        cb.src[3] = Wk;     cb.dst[3] = p_bw1;  cb.N[3] = 512;       cb.xt[3] = 16;
        cb.src[4] = Wv;     cb.dst[4] = p_bw2;  cb.N[4] = 512;       cb.xt[4] = 16;
        cb.src[5] = maa_w1; cb.dst[5] = p_bws1; cb.N[5] = 5 * LMAA_; cb.xt[5] = 8;
        cb.src[6] = dec_w1; cb.dst[6] = p_bws2; cb.N[6] = LDEC_;     cb.xt[6] = 8;
        k_conv_all<<<dim3(240, 64), cw>>>(cb);
    }

    // 1) token shift -> sx (f32) + ba_xxx (bf16 split)
    k_shift<<<GE, EW>>>(x, state, ns, maa_x);

    // 2) t1 = tanh(xxx @ maa_w1) [T,160]: split-K 4 (z entries) + reduce
    {
        TB tb = {};
        for (int z = 0; z < SPLITK; z++) {
            tb.A[z] = p_ba_xxx; tb.B[z] = p_bws1;
            tb.Cc[z] = p_part + (size_t)z * T_ * (5 * LMAA_);
            tb.N[z] = 5 * LMAA_; tb.ldc[z] = 5 * LMAA_; tb.epi[z] = EPI_NONE;
            tb.nch[z] = 96 / SPLITK; tb.kc0[z] = z * (96 / SPLITK);
        }
        hgemm<<<dim3(2, 16, SPLITK), blk, HG_SMEM>>>(tb);
        int n = T_ * 5 * LMAA_;
        k_red_tanh<<<(n + EW - 1) / EW, EW>>>(p_part, p_t1, n, n);
    }

    // 3) MIX (FFMA2, K=32): writes 5 bf16-split activation buffers
    {
        Batch bt = {};
        const float* vecs[5] = { maa_r, maa_k, maa_v, maa_w, maa_g };
        void* outs[5] = { p_ba_r, p_ba_k, p_ba_v, p_ba_w, p_ba_g };
        for (int z = 0; z < 5; z++) {
            bt.A[z]  = p_t1 + z * LMAA_;
            bt.B[z]  = maa_w2 + (size_t)z * LMAA_ * C_;
            bt.Cc[z] = outs[z];
            bt.vec[z] = vecs[z];
        }
        gemm128<EPI_MIX><<<dim3(C_ / 128, T_ / 128, 5), blk>>>(bt, 5 * LMAA_, C_, C_, C_, LMAA_, x, p_sx);
    }

    // 4) r + gate + k + v + dec-splitK(4) in ONE launch (z=8)
    {
        TB tb = {};
        tb.A[0] = p_ba_r; tb.B[0] = p_bwA; tb.Cc[0] = p_r;    tb.N[0] = C_;  tb.ldc[0] = C_;  tb.epi[0] = EPI_NONE; tb.nch[0] = 96; tb.kc0[0] = 0;
        tb.A[1] = p_ba_g; tb.B[1] = p_bwB; tb.Cc[1] = p_gate; tb.N[1] = C_;  tb.ldc[1] = C_;  tb.epi[1] = EPI_SIG;  tb.nch[1] = 96; tb.kc0[1] = 0;
        tb.A[2] = p_ba_k; tb.B[2] = p_bw1; tb.Cc[2] = p_k;    tb.N[2] = 512; tb.ldc[2] = 512; tb.epi[2] = EPI_NONE; tb.nch[2] = 96; tb.kc0[2] = 0;
        tb.A[3] = p_ba_v; tb.B[3] = p_bw2; tb.Cc[3] = p_v;    tb.N[3] = 512; tb.ldc[3] = 512; tb.epi[3] = EPI_NONE; tb.nch[3] = 96; tb.kc0[3] = 0;
        for (int z = 0; z < SPLITK; z++) {
            tb.A[4 + z] = p_ba_w; tb.B[4 + z] = p_bws2;
            tb.Cc[4 + z] = p_part + (size_t)z * T_ * LDEC_;
            tb.N[4 + z] = LDEC_; tb.ldc[4 + z] = LDEC_; tb.epi[4 + z] = EPI_NONE;
            tb.nch[4 + z] = 96 / SPLITK; tb.kc0[4 + z] = z * (96 / SPLITK);
        }
        hgemm<<<dim3(16, 16, 8), blk, HG_SMEM>>>(tb);
    }

    // 5) t2 = tanh(dec partial sums)
    {
        int n = T_ * LDEC_;
        k_red_tanh<<<(n + EW - 1) / EW, EW>>>(p_part, p_t2, n, n);
    }

    // 6) ew = exp(max(-exp(t2@dec_w2 + tdecay), -5)) AND keff = k*(1-ew)  (FFMA2, K=64)
    {
        Batch bt = {};
        bt.A[0] = p_t2; bt.B[0] = dec_w2; bt.Cc[0] = p_ew; bt.vec[0] = tdecay;
        gemm128<EPI_DECAY><<<dim3(C_ / 128, T_ / 128, 1), blk>>>(bt, LDEC_, C_, C_, C_, LDEC_, nullptr, nullptr);
    }

    // 7) scan: writes gated output as bf16 split into ba_r (reused)
    k_scan<<<H_, 512, SCAN_SMEM>>>(state, ns, p_ba_r);

    // 8) final projection: dout = (out*gate) @ Wo
    {
        TB tb = {};
        tb.A[0] = p_ba_r; tb.B[0] = p_bwC; tb.Cc[0] = dout;
        tb.N[0] = C_; tb.ldc[0] = C_; tb.epi[0] = EPI_NONE; tb.nch[0] = 96; tb.kc0[0] = 0;
        hgemm<<<dim3(16, 16, 1), blk, HG_SMEM>>>(tb);
    }

    // 9) new_state (only if the harness expects both outputs)
    if (out_size >= T_ * C_ + (S_ + 1) * C_) {
        int n = H_ * S_ * S_;
        k_state<<<(n + EW - 1) / EW, EW>>>(dout, x, lenp);
    }
}

// round 16
// speedup vs baseline: 1.5223x; 1.0444x over previous
#include <cuda_runtime.h>
#include <cuda_bf16.h>
#include <math.h>
#include <stdint.h>

#define T_ 2048
#define C_ 2048
#define H_ 32
#define S_ 64
#define HKV_ 8
#define LMAA_ 32
#define LDEC_ 64
#define K2_ (2 * C_)   // 4096: [hi|lo] storage; GEMM K' = 96 chunks with remap
#define SPLITK 4

// ---------------- f32 scratch ----------------
__device__ float g_sx [T_*C_];
__device__ float g_t1 [T_*5*LMAA_];
__device__ float g_t2 [T_*LDEC_];
__device__ float g_r  [T_*C_];
__device__ float g_k  [T_*HKV_*S_];
__device__ float g_v  [T_*HKV_*S_];
__device__ float g_ew [T_*C_];
__device__ float g_keff[T_*C_];
__device__ float g_gate[T_*C_];
__device__ float g_sfin[H_*S_*S_];
__device__ float g_part[SPLITK * T_ * (5*LMAA_ + LDEC_)];

// ---------------- bf16 2-segment buffers: rows = [hi(2048) | lo(2048)] ----------------
// GEMM emulates 3-term split: A segs (hi,hi,lo) x W segs (hi,lo,hi) via chunk remap.
__device__ __align__(128) __nv_bfloat16 g_ba_xxx[(size_t)T_ * K2_];
__device__ __align__(128) __nv_bfloat16 g_ba_r  [(size_t)T_ * K2_];   // xr, later reused for out
__device__ __align__(128) __nv_bfloat16 g_ba_k  [(size_t)T_ * K2_];
__device__ __align__(128) __nv_bfloat16 g_ba_v  [(size_t)T_ * K2_];
__device__ __align__(128) __nv_bfloat16 g_ba_w  [(size_t)T_ * K2_];
__device__ __align__(128) __nv_bfloat16 g_ba_g  [(size_t)T_ * K2_];
__device__ __align__(128) __nv_bfloat16 g_bwA[(size_t)2048 * K2_];    // Wq
__device__ __align__(128) __nv_bfloat16 g_bwB[(size_t)2048 * K2_];    // Wg
__device__ __align__(128) __nv_bfloat16 g_bwC[(size_t)2048 * K2_];    // Wo
__device__ __align__(128) __nv_bfloat16 g_bw1[(size_t)512 * K2_];     // Wk
__device__ __align__(128) __nv_bfloat16 g_bw2[(size_t)512 * K2_];     // Wv
__device__ __align__(128) __nv_bfloat16 g_bws1[(size_t)256 * K2_];    // maa_w1 (160->256)
__device__ __align__(128) __nv_bfloat16 g_bws2[(size_t)256 * K2_];    // dec_w1 (64->256)

// ---------------- epilogue ids ----------------
#define EPI_NONE  0
#define EPI_TANH  1
#define EPI_SIG   2
#define EPI_MIX   3
#define EPI_DECAY 4

// ---------------- mma.sync helpers ----------------
__device__ __forceinline__ uint32_t smem_u32(const void* p) {
    uint32_t a;
    asm("{ .reg .u64 t; cvta.to.shared.u64 t, %1; cvt.u32.u64 %0, t; }" : "=r"(a) : "l"(p));
    return a;
}
__device__ __forceinline__ void cp_async16(uint32_t saddr, const void* g) {
    asm volatile("cp.async.cg.shared.global [%0], [%1], 16;" :: "r"(saddr), "l"(g) : "memory");
}
__device__ __forceinline__ void cp_async4(uint32_t saddr, const void* g) {
    asm volatile("cp.async.ca.shared.global [%0], [%1], 4;" :: "r"(saddr), "l"(g) : "memory");
}
__device__ __forceinline__ void ldmatrix_x4(uint32_t* r, uint32_t addr) {
    asm volatile("ldmatrix.sync.aligned.m8n8.x4.shared.b16 {%0,%1,%2,%3}, [%4];"
        : "=r"(r[0]), "=r"(r[1]), "=r"(r[2]), "=r"(r[3]) : "r"(addr));
}
__device__ __forceinline__ void mma16816(float* c, const uint32_t* a, uint32_t b0, uint32_t b1) {
    asm volatile("mma.sync.aligned.m16n8k16.row.col.f32.bf16.bf16.f32 "
        "{%0,%1,%2,%3}, {%4,%5,%6,%7}, {%8,%9}, {%0,%1,%2,%3};"
        : "+f"(c[0]), "+f"(c[1]), "+f"(c[2]), "+f"(c[3])
        : "r"(a[0]), "r"(a[1]), "r"(a[2]), "r"(a[3]), "r"(b0), "r"(b1));
}

struct TB {
    const __nv_bfloat16* A[8];
    const __nv_bfloat16* B[8];
    float*               Cc[8];
    int N[8];
    int ldc[8];
    int epi[8];
    int nch[8];   // K chunks (of 64) in the VIRTUAL K'=6144 space
    int kc0[8];   // start chunk (split-K)
};

// ---------------- HMMA bf16 GEMM: C = A3[M,K'] @ W3[N,K']^T (virtual K'=6144) ----------
// Storage is 2-seg [hi|lo] (K2 per row); virtual chunk ck in [0,96) maps:
//   A: ck<32 -> hi(ck), ck<64 -> hi(ck-32), else lo(ck-32)  => ak = ck<32 ? ck : ck-32
//   W: ck<32 -> hi(ck), ck<64 -> lo(ck),    else hi(ck-64)  => wk = ck<64 ? ck : ck-64
// 128x128 CTA tile, 8 warps (2m x 4n), warp 64x32 m16n8k16, BK=64, 3-stage cp.async.
__global__ __launch_bounds__(256, 2)
void hgemm(TB bt)
{
    const int z = blockIdx.z;
    const __nv_bfloat16* __restrict__ Ag = bt.A[z];
    const __nv_bfloat16* __restrict__ Bg = bt.B[z];
    float* __restrict__ Cg = bt.Cc[z];
    const int N = bt.N[z], ldc = bt.ldc[z], epi = bt.epi[z];
    const int nch = bt.nch[z], kc0 = bt.kc0[z];
    if (blockIdx.x * 128 >= N) return;

    extern __shared__ char smem[];
    const uint32_t sbase = smem_u32(smem);   // 3 stages x (A 16KB | B 16KB)

    const int tid  = threadIdx.x;
    const int lane = tid & 31;
    const int wid  = tid >> 5;
    const int wm   = wid >> 2;    // 0..1
    const int wn   = wid & 3;     // 0..3
    const int bx = blockIdx.x, by = blockIdx.y;

    float acc[4][4][4];
    #pragma unroll
    for (int i = 0; i < 4; i++)
        #pragma unroll
        for (int j = 0; j < 4; j++)
            #pragma unroll
            for (int k = 0; k < 4; k++) acc[i][j][k] = 0.f;

    const __nv_bfloat16* Abase = Ag + (size_t)(by * 128) * K2_;
    const __nv_bfloat16* Bbase = Bg + (size_t)(bx * 128) * K2_;

    auto load_stage = [&](int kt, int s) {
        const uint32_t sa = sbase + s * 32768;
        const int ck = kc0 + kt;
        const int ak = (ck < 32) ? ck : ck - 32;
        const int wk = (ck < 64) ? ck : ck - 64;
        const __nv_bfloat16* Agk = Abase + (size_t)ak * 64;
        const __nv_bfloat16* Bgk = Bbase + (size_t)wk * 64;
        #pragma unroll
        for (int q = 0; q < 4; q++) {
            const int c = q * 256 + tid;
            const int row = c >> 3, j = c & 7;
            uint32_t off = (uint32_t)(row * 128 + j * 16);
            off ^= (off >> 3) & 0x70;
            cp_async16(sa + off,         Agk + (size_t)row * K2_ + j * 8);
            cp_async16(sa + 16384 + off, Bgk + (size_t)row * K2_ + j * 8);
        }
        asm volatile("cp.async.commit_group;" ::: "memory");
    };

    const int a_roff = (wm * 64 + (lane & 15)) * 128 + (lane >> 4) * 16;
    const int b_roff = (wn * 32 + (lane & 7) + ((lane >> 4) << 3)) * 128 + ((lane >> 3) & 1) * 16;

    auto compute = [&](int s) {
        const uint32_t sa = sbase + s * 32768;
        const uint32_t sbb = sa + 16384;
        #pragma unroll
        for (int ks = 0; ks < 4; ks++) {
            uint32_t bf2[2][4];
            #pragma unroll
            for (int nt2 = 0; nt2 < 2; nt2++) {
                uint32_t off = (uint32_t)(b_roff + nt2 * 16 * 128 + ks * 32);
                off ^= (off >> 3) & 0x70;
                ldmatrix_x4(bf2[nt2], sbb + off);
            }
            uint32_t af[4][4];
            #pragma unroll
            for (int mt = 0; mt < 4; mt++) {
                uint32_t off = (uint32_t)(a_roff + mt * 16 * 128 + ks * 32);
                off ^= (off >> 3) & 0x70;
                ldmatrix_x4(af[mt], sa + off);
            }
            #pragma unroll
            for (int mt = 0; mt < 4; mt++)
                #pragma unroll
                for (int nt = 0; nt < 4; nt++)
                    mma16816(acc[mt][nt], af[mt],
                             bf2[nt >> 1][(nt & 1) * 2], bf2[nt >> 1][(nt & 1) * 2 + 1]);
        }
    };

    load_stage(0, 0);
    load_stage(1, 1);

    for (int kt = 0; kt < nch; kt++) {
        asm volatile("cp.async.wait_group 1;" ::: "memory");
        __syncthreads();
        if (kt + 2 < nch) load_stage(kt + 2, (kt + 2) % 3);
        else asm volatile("cp.async.commit_group;" ::: "memory");
        compute(kt % 3);
    }

    // epilogue (runtime epi: NONE / TANH / SIG)
    #pragma unroll
    for (int mt = 0; mt < 4; mt++) {
        #pragma unroll
        for (int hrow = 0; hrow < 2; hrow++) {
            const int row = by * 128 + wm * 64 + mt * 16 + hrow * 8 + (lane >> 2);
            float* crow = Cg + (size_t)row * ldc;
            #pragma unroll
            for (int nt = 0; nt < 4; nt++) {
                const int col = bx * 128 + wn * 32 + nt * 8 + (lane & 3) * 2;
                if (col >= N) continue;
                float v0 = acc[mt][nt][hrow * 2 + 0];
                float v1 = acc[mt][nt][hrow * 2 + 1];
                if (epi == EPI_TANH) { v0 = tanhf(v0); v1 = tanhf(v1); }
                else if (epi == EPI_SIG) { v0 = 1.f/(1.f+expf(-v0)); v1 = 1.f/(1.f+expf(-v1)); }
                *(float2*)&crow[col] = make_float2(v0, v1);
            }
        }
    }
}

// ---------------- split-K reducer + tanh ----------------
__global__ void k_red_tanh(const float* __restrict__ part, float* __restrict__ out,
                           int n, int stride)
{
    int i = blockIdx.x * blockDim.x + threadIdx.x;
    if (i >= n) return;
    float s = part[i] + part[(size_t)stride + i]
            + part[(size_t)2 * stride + i] + part[(size_t)3 * stride + i];
    out[i] = tanhf(s);
}

// ---------------- batched weight conversion (ALL weights, one launch) ----------------
// src[2048 x N] f32 -> dst[Npad x 4096] bf16 rows n: [hi | lo], transposed.
struct CB {
    const float*   src[7];
    __nv_bfloat16* dst[7];
    int            N[7];
    int            xt[7];
};

__global__ void k_conv_all(CB cb)
{
    __shared__ float tile[32][33];
    int bx = blockIdx.x;
    int w = 0;
    while (bx >= cb.xt[w]) { bx -= cb.xt[w]; w++; }
    const float* __restrict__ src = cb.src[w];
    __nv_bfloat16* __restrict__ dst = cb.dst[w];
    const int N = cb.N[w];

    const int n0 = bx * 32;
    const int k0 = blockIdx.y * 32;
    const int tx = threadIdx.x, ty = threadIdx.y;  // (32, 8)
    #pragma unroll
    for (int yy = 0; yy < 32; yy += 8) {
        int n = n0 + tx, k = k0 + ty + yy;
        tile[ty + yy][tx] = (n < N) ? src[(size_t)k * N + n] : 0.f;
    }
    __syncthreads();
    #pragma unroll
    for (int yy = 0; yy < 32; yy += 8) {
        int n = n0 + ty + yy;
        int k = k0 + tx;
        float a = tile[tx][ty + yy];
        __nv_bfloat16 hi = __float2bfloat16(a);
        __nv_bfloat16 lo = __float2bfloat16(a - __bfloat162float(hi));
        size_t base = (size_t)n * K2_;
        dst[base + k] = hi;
        dst[base + C_ + k] = lo;
    }
}

// ---------------- FFMA2 GEMM (MIX K=32 -> bf16 [hi|lo] out, DECAY K=64 -> ew + keff) ----
struct Batch {
    const float* A[8];
    const float* B[8];
    void*        Cc[8];
    const float* vec[8];
};

template<int EPI>
__global__ __launch_bounds__(256, 2)
void gemm128(Batch bt, int lda, int ldb, int ldc, int N, int K,
             const float* __restrict__ aux1, const float* __restrict__ aux2)
{
    __shared__ float2 As[2][16][128];
    __shared__ float  Bs[2][16][128];

    const int z = blockIdx.z;
    const float* __restrict__ A   = bt.A[z];
    const float* __restrict__ B   = bt.B[z];
    const float* __restrict__ vec = bt.vec[z];

    const int tid = threadIdx.x;
    const int bx = blockIdx.x, by = blockIdx.y;
    const int arow = tid >> 1,  acol = (tid & 1) * 8;
    const int brow = tid >> 4,  bcol = (tid & 15) * 8;
    const int tx = tid & 15,    ty = tid >> 4;

    unsigned long long acc[8][4];
    #pragma unroll
    for (int i = 0; i < 8; i++)
        #pragma unroll
        for (int j = 0; j < 4; j++) acc[i][j] = 0ULL;

    const float* Ap = A + (size_t)(by * 128 + arow) * lda + acol;
    const int gcolb = bx * 128 + bcol;

    float4 a0, a1, b0, b1;
    auto loadAB = [&](int k0) {
        a0 = *(const float4*)(Ap + k0);
        a1 = *(const float4*)(Ap + k0 + 4);
        const float* bp = B + (size_t)(k0 + brow) * ldb + gcolb;
        b0 = *(const float4*)bp;
        b1 = *(const float4*)(bp + 4);
    };
    auto storeAB = [&](int buf) {
        As[buf][acol + 0][arow] = make_float2(a0.x, a0.x);
        As[buf][acol + 1][arow] = make_float2(a0.y, a0.y);
        As[buf][acol + 2][arow] = make_float2(a0.z, a0.z);
        As[buf][acol + 3][arow] = make_float2(a0.w, a0.w);
        As[buf][acol + 4][arow] = make_float2(a1.x, a1.x);
        As[buf][acol + 5][arow] = make_float2(a1.y, a1.y);
        As[buf][acol + 6][arow] = make_float2(a1.z, a1.z);
        As[buf][acol + 7][arow] = make_float2(a1.w, a1.w);
        *(float4*)&Bs[buf][brow][bcol]     = b0;
        *(float4*)&Bs[buf][brow][bcol + 4] = b1;
    };

    loadAB(0);
    storeAB(0);
    __syncthreads();

    const int nt = K >> 4;
    for (int kt = 0; kt < nt; kt++) {
        const int cur = kt & 1;
        if (kt + 1 < nt) loadAB((kt + 1) << 4);

        #pragma unroll
        for (int kk = 0; kk < 16; kk++) {
            unsigned long long a2[8], b2[4];
            const ulonglong2* ap = (const ulonglong2*)&As[cur][kk][ty * 8];
            ulonglong2 w;
            w = ap[0]; a2[0] = w.x; a2[1] = w.y;
            w = ap[1]; a2[2] = w.x; a2[3] = w.y;
            w = ap[2]; a2[4] = w.x; a2[5] = w.y;
            w = ap[3]; a2[6] = w.x; a2[7] = w.y;
            const ulonglong2* bp2 = (const ulonglong2*)&Bs[cur][kk][tx * 8];
            w = bp2[0]; b2[0] = w.x; b2[1] = w.y;
            w = bp2[1]; b2[2] = w.x; b2[3] = w.y;
            #pragma unroll
            for (int i = 0; i < 8; i++)
                #pragma unroll
                for (int j = 0; j < 4; j++)
                    asm("fma.rn.f32x2 %0, %1, %2, %0;"
                        : "+l"(acc[i][j]) : "l"(a2[i]), "l"(b2[j]));
        }

        if (kt + 1 < nt) storeAB(cur ^ 1);
        __syncthreads();
    }

    #pragma unroll
    for (int i = 0; i < 8; i++) {
        const int row = by * 128 + ty * 8 + i;
        #pragma unroll
        for (int j = 0; j < 4; j++) {
            const int col = bx * 128 + tx * 8 + 2 * j;
            float v0 = __uint_as_float((unsigned)(acc[i][j] & 0xffffffffULL));
            float v1 = __uint_as_float((unsigned)(acc[i][j] >> 32));
            if (EPI == EPI_MIX) {
                size_t idx = (size_t)row * C_ + col;
                v0 = aux1[idx]     + aux2[idx]     * (vec[col]     + v0);
                v1 = aux1[idx + 1] + aux2[idx + 1] * (vec[col + 1] + v1);
                __nv_bfloat16 h0 = __float2bfloat16(v0);
                __nv_bfloat16 h1 = __float2bfloat16(v1);
                __nv_bfloat16 l0 = __float2bfloat16(v0 - __bfloat162float(h0));
                __nv_bfloat16 l1 = __float2bfloat16(v1 - __bfloat162float(h1));
                __nv_bfloat162 hh; hh.x = h0; hh.y = h1;
                __nv_bfloat162 ll; ll.x = l0; ll.y = l1;
                __nv_bfloat16* bout = (__nv_bfloat16*)bt.Cc[z];
                size_t base = (size_t)row * K2_;
                *(__nv_bfloat162*)&bout[base + col]      = hh;
                *(__nv_bfloat162*)&bout[base + C_ + col] = ll;
            } else {  // EPI_DECAY: write ew AND keff = k*(1-ew)
                float* crow = (float*)bt.Cc[z] + (size_t)row * ldc;
                float lw0 = fmaxf(-expf(v0 + vec[col]), -5.0f);
                float lw1 = fmaxf(-expf(v1 + vec[col + 1]), -5.0f);
                float e0 = expf(lw0), e1 = expf(lw1);
                *(float2*)&crow[col] = make_float2(e0, e1);
                int hh2 = col >> 6, ss = col & 63;
                float2 kv = *(const float2*)&g_k[(size_t)row * 512 + (hh2 >> 2) * 64 + ss];
                *(float2*)&g_keff[(size_t)row * C_ + col] =
                    make_float2(kv.x * (1.f - e0), kv.y * (1.f - e1));
            }
        }
    }
}

// ---------------- token shift: writes sx (f32) + xxx (bf16 [hi|lo]) ----------------
__global__ void k_shift(const float* __restrict__ x, const float* __restrict__ state,
                        const unsigned char* __restrict__ ns,
                        const float* __restrict__ maa_x)
{
    int idx = blockIdx.x * blockDim.x + threadIdx.x;
    if (idx >= T_ * C_) return;
    int t = idx >> 11;
    int c = idx & 2047;
    float prev = (t == 0) ? state[c] : x[idx - C_];
    if (ns[t]) prev = 0.f;
    float s = prev - x[idx];
    g_sx[idx] = s;
    float v = x[idx] + s * maa_x[c];
    __nv_bfloat16 hi = __float2bfloat16(v);
    __nv_bfloat16 lo = __float2bfloat16(v - __bfloat162float(hi));
    size_t base = (size_t)t * K2_;
    g_ba_xxx[base + c]      = hi;
    g_ba_xxx[base + C_ + c] = lo;
}

// ---------------- RWKV scan v3: cp.async ring, 2 barriers per 8 steps ----------------
#define SCAN_SLOT 320                          // floats per slot: r|keff|ew|v|gate
#define SCAN_SMEM (32*SCAN_SLOT*4 + 8*512*4 + T_)

__global__ __launch_bounds__(512)
void k_scan(const float* __restrict__ state, const unsigned char* __restrict__ ns,
            __nv_bfloat16* __restrict__ out_split)
{
    extern __shared__ char sm[];
    float* ring = (float*)sm;                                   // [32][320]
    float* pbuf = (float*)(sm + 32 * SCAN_SLOT * 4);            // [8][512]
    unsigned char* nsh = (unsigned char*)(sm + 32 * SCAN_SLOT * 4 + 8 * 512 * 4);

    const int h = blockIdx.x;
    const int tid = threadIdx.x;
    const int vcol = tid >> 3;
    const int kg = tid & 7;

    unsigned long long s2[4];
    #pragma unroll
    for (int j2 = 0; j2 < 4; j2++) {
        float slo = state[C_ + h * 4096 + (kg * 8 + 2 * j2) * 64 + vcol];
        float shi = state[C_ + h * 4096 + (kg * 8 + 2 * j2 + 1) * 64 + vcol];
        asm("mov.b64 %0, {%1, %2};" : "=l"(s2[j2]) : "f"(slo), "f"(shi));
    }

    for (int i = tid; i < T_; i += 512) nsh[i] = ns[i];

    const int a  = tid >> 6;
    const int li = tid & 63;
    const bool loader = (a < 5);
    const float* src = nullptr;
    int stride = C_;
    if (a == 0)      src = g_r    + (size_t)h * 64 + li;
    else if (a == 1) src = g_keff + (size_t)h * 64 + li;
    else if (a == 2) src = g_ew   + (size_t)h * 64 + li;
    else if (a == 3) { src = g_v + (size_t)(h >> 2) * 64 + li; stride = 512; }
    else if (a == 4) src = g_gate + (size_t)h * 64 + li;

    const uint32_t sring = smem_u32(ring);
    const uint32_t dbase = (uint32_t)(a * 64 + li) * 4;

    auto issue8 = [&](int tbase) {
        if (loader) {
            #pragma unroll
            for (int p = 0; p < 8; p++) {
                int t = tbase + p;
                cp_async4(sring + (uint32_t)((t & 31) * SCAN_SLOT) * 4 + dbase,
                          src + (size_t)t * stride);
            }
        }
        asm volatile("cp.async.commit_group;" ::: "memory");
    };

    issue8(0);
    issue8(8);

    for (int S = 0; S < T_ / 8; S++) {
        const int t0 = S * 8;
        if (t0 + 16 < T_) issue8(t0 + 16);
        else asm volatile("cp.async.commit_group;" ::: "memory");
        asm volatile("cp.async.wait_group 2;" ::: "memory");
        __syncthreads();

        #pragma unroll
        for (int p = 0; p < 8; p++) {
            const int t = t0 + p;
            const float* Sl = ring + (t & 31) * SCAN_SLOT;

            float vv = Sl[3 * 64 + vcol];
            unsigned long long vv2;
            asm("mov.b64 %0, {%1, %1};" : "=l"(vv2) : "f"(vv));

            const bool reset = (nsh[t] != 0);

            const ulonglong2* rp = (const ulonglong2*)&Sl[0 * 64 + kg * 8];
            const ulonglong2* kp = (const ulonglong2*)&Sl[1 * 64 + kg * 8];
            const ulonglong2* wp = (const ulonglong2*)&Sl[2 * 64 + kg * 8];
            ulonglong2 rA = rp[0], rB = rp[1];
            ulonglong2 kA = kp[0], kB = kp[1];
            ulonglong2 wA = wp[0], wB = wp[1];
            unsigned long long r2[4] = { rA.x, rA.y, rB.x, rB.y };
            unsigned long long k2[4] = { kA.x, kA.y, kB.x, kB.y };
            unsigned long long w2[4] = { wA.x, wA.y, wB.x, wB.y };

            unsigned long long ps2 = 0ULL;
            #pragma unroll
            for (int j2 = 0; j2 < 4; j2++) {
                if (reset) s2[j2] = 0ULL;
                unsigned long long kv2;
                asm("mul.rn.f32x2 %0, %1, %2;"     : "=l"(kv2)    : "l"(k2[j2]), "l"(vv2));
                asm("fma.rn.f32x2 %0, %1, %2, %3;" : "=l"(s2[j2]) : "l"(s2[j2]), "l"(w2[j2]), "l"(kv2));
                asm("fma.rn.f32x2 %0, %1, %2, %0;" : "+l"(ps2)    : "l"(r2[j2]), "l"(s2[j2]));
            }

            float plo = __uint_as_float((unsigned)(ps2 & 0xffffffffULL));
            float phi = __uint_as_float((unsigned)(ps2 >> 32));
            pbuf[p * 512 + tid] = plo + phi;
        }
        __syncthreads();

        {
            const int st = tid >> 6;
            const int vc = tid & 63;
            const float4* p4 = (const float4*)&pbuf[st * 512 + vc * 8];
            float4 x0 = p4[0], x1 = p4[1];
            float o = ((x0.x + x0.y) + (x0.z + x0.w)) + ((x1.x + x1.y) + (x1.z + x1.w));
            const int t = t0 + st;
            o *= ring[(t & 31) * SCAN_SLOT + 4 * 64 + vc];
            __nv_bfloat16 hi = __float2bfloat16(o);
            __nv_bfloat16 lo = __float2bfloat16(o - __bfloat162float(hi));
            size_t base = (size_t)t * K2_;
            int c = h * 64 + vc;
            out_split[base + c]      = hi;
            out_split[base + C_ + c] = lo;
        }
    }

    #pragma unroll
    for (int j2 = 0; j2 < 4; j2++) {
        float slo = __uint_as_float((unsigned)(s2[j2] & 0xffffffffULL));
        float shi = __uint_as_float((unsigned)(s2[j2] >> 32));
        g_sfin[h * 4096 + (kg * 8 + 2 * j2) * 64 + vcol]     = slo;
        g_sfin[h * 4096 + (kg * 8 + 2 * j2 + 1) * 64 + vcol] = shi;
    }
}

// ---------------- new_state writer ----------------
__global__ void k_state(float* __restrict__ dout, const float* __restrict__ x,
                        const int* __restrict__ lenp)
{
    int idx = blockIdx.x * blockDim.x + threadIdx.x;
    int L = lenp ? lenp[0] : T_;
    if (idx < C_)
        dout[(size_t)T_ * C_ + idx] = x[(size_t)(L - 1) * C_ + idx];
    if (idx < H_ * S_ * S_)
        dout[(size_t)T_ * C_ + C_ + idx] = g_sfin[idx];
}

// ---------------- host-side orchestration ----------------
template <typename Sym>
static void* devaddr_v(Sym& sym) {
    void* p = nullptr;
    cudaGetSymbolAddress(&p, sym);
    return p;
}

#define HG_SMEM (3 * 32768)

extern "C" void kernel_launch(void* const* d_in, const int* in_sizes, int n_in,
                              void* d_out, int out_size)
{
    int i = 0;
    const float* x       = (const float*)d_in[i++];
    const float* state   = (const float*)d_in[i++];
    const unsigned char* ns = (const unsigned char*)d_in[i++];
    const int* lenp = nullptr;
    if (n_in >= 20) { lenp = (const int*)d_in[i++]; }
    const float* maa_x = (const float*)d_in[i++];
    const float* maa_r = (const float*)d_in[i++];
    const float* maa_k = (const float*)d_in[i++];
    const float* maa_v = (const float*)d_in[i++];
    const float* maa_w = (const float*)d_in[i++];
    const float* maa_g = (const float*)d_in[i++];
    const float* maa_w1 = (const float*)d_in[i++];  // [C, 160]
    const float* maa_w2 = (const float*)d_in[i++];  // [5, 32, C]
    const float* tdecay = (const float*)d_in[i++];  // [C]
    const float* dec_w1 = (const float*)d_in[i++];  // [C, 64]
    const float* dec_w2 = (const float*)d_in[i++];  // [64, C]
    const float* Wq = (const float*)d_in[i++];      // [C, C]
    const float* Wk = (const float*)d_in[i++];      // [C, 512]
    const float* Wv = (const float*)d_in[i++];      // [C, 512]
    const float* Wg = (const float*)d_in[i++];      // [C, C]
    const float* Wo = (const float*)d_in[i++];      // [C, C]
    float* dout = (float*)d_out;

    float* p_sx   = (float*)devaddr_v(g_sx);
    float* p_t1   = (float*)devaddr_v(g_t1);
    float* p_t2   = (float*)devaddr_v(g_t2);
    float* p_r    = (float*)devaddr_v(g_r);
    float* p_k    = (float*)devaddr_v(g_k);
    float* p_v    = (float*)devaddr_v(g_v);
    float* p_ew   = (float*)devaddr_v(g_ew);
    float* p_gate = (float*)devaddr_v(g_gate);
    float* p_part = (float*)devaddr_v(g_part);
    __nv_bfloat16* p_ba_xxx = (__nv_bfloat16*)devaddr_v(g_ba_xxx);
    __nv_bfloat16* p_ba_r   = (__nv_bfloat16*)devaddr_v(g_ba_r);
    __nv_bfloat16* p_ba_k   = (__nv_bfloat16*)devaddr_v(g_ba_k);
    __nv_bfloat16* p_ba_v   = (__nv_bfloat16*)devaddr_v(g_ba_v);
    __nv_bfloat16* p_ba_w   = (__nv_bfloat16*)devaddr_v(g_ba_w);
    __nv_bfloat16* p_ba_g   = (__nv_bfloat16*)devaddr_v(g_ba_g);
    __nv_bfloat16* p_bwA  = (__nv_bfloat16*)devaddr_v(g_bwA);
    __nv_bfloat16* p_bwB  = (__nv_bfloat16*)devaddr_v(g_bwB);
    __nv_bfloat16* p_bwC  = (__nv_bfloat16*)devaddr_v(g_bwC);
    __nv_bfloat16* p_bw1  = (__nv_bfloat16*)devaddr_v(g_bw1);
    __nv_bfloat16* p_bw2  = (__nv_bfloat16*)devaddr_v(g_bw2);
    __nv_bfloat16* p_bws1 = (__nv_bfloat16*)devaddr_v(g_bws1);
    __nv_bfloat16* p_bws2 = (__nv_bfloat16*)devaddr_v(g_bws2);

    cudaFuncSetAttribute(hgemm, cudaFuncAttributeMaxDynamicSharedMemorySize, HG_SMEM);
    cudaFuncSetAttribute(k_scan, cudaFuncAttributeMaxDynamicSharedMemorySize, SCAN_SMEM);

    const int EW = 256;
    const int GE = (T_ * C_ + EW - 1) / EW;
    dim3 blk(256);
    dim3 cw(32, 8);

    // 0) ALL weight conversions in one launch
    {
        CB cb = {};
        cb.src[0] = Wq;     cb.dst[0] = p_bwA;  cb.N[0] = C_;        cb.xt[0] = 64;
        cb.src[1] = Wg;     cb.dst[1] = p_bwB;  cb.N[1] = C_;        cb.xt[1] = 64;
        cb.src[2] = Wo;     cb.dst[2] = p_bwC;  cb.N[2] = C_;        cb.xt[2] = 64;
        cb.src[3] = Wk;     cb.dst[3] = p_bw1;  cb.N[3] = 512;       cb.xt[3] = 16;
        cb.src[4] = Wv;     cb.dst[4] = p_bw2;  cb.N[4] = 512;       cb.xt[4] = 16;
        cb.src[5] = maa_w1; cb.dst[5] = p_bws1; cb.N[5] = 5 * LMAA_; cb.xt[5] = 8;
        cb.src[6] = dec_w1; cb.dst[6] = p_bws2; cb.N[6] = LDEC_;     cb.xt[6] = 8;
        k_conv_all<<<dim3(240, 64), cw>>>(cb);
    }

    // 1) token shift -> sx (f32) + ba_xxx (bf16 [hi|lo])
    k_shift<<<GE, EW>>>(x, state, ns, maa_x);

    // 2) t1 = tanh(xxx @ maa_w1) [T,160]: split-K 4 + reduce
    {
        TB tb = {};
        for (int z = 0; z < SPLITK; z++) {
            tb.A[z] = p_ba_xxx; tb.B[z] = p_bws1;
            tb.Cc[z] = p_part + (size_t)z * T_ * (5 * LMAA_);
            tb.N[z] = 5 * LMAA_; tb.ldc[z] = 5 * LMAA_; tb.epi[z] = EPI_NONE;
            tb.nch[z] = 96 / SPLITK; tb.kc0[z] = z * (96 / SPLITK);
        }
        hgemm<<<dim3(2, 16, SPLITK), blk, HG_SMEM>>>(tb);
        int n = T_ * 5 * LMAA_;
        k_red_tanh<<<(n + EW - 1) / EW, EW>>>(p_part, p_t1, n, n);
    }

    // 3) MIX (FFMA2, K=32): writes 5 bf16 [hi|lo] activation buffers
    {
        Batch bt = {};
        const float* vecs[5] = { maa_r, maa_k, maa_v, maa_w, maa_g };
        void* outs[5] = { p_ba_r, p_ba_k, p_ba_v, p_ba_w, p_ba_g };
        for (int z = 0; z < 5; z++) {
            bt.A[z]  = p_t1 + z * LMAA_;
            bt.B[z]  = maa_w2 + (size_t)z * LMAA_ * C_;
            bt.Cc[z] = outs[z];
            bt.vec[z] = vecs[z];
        }
        gemm128<EPI_MIX><<<dim3(C_ / 128, T_ / 128, 5), blk>>>(bt, 5 * LMAA_, C_, C_, C_, LMAA_, x, p_sx);
    }

    // 4) r + gate + k + v + dec-splitK(4) in ONE launch (z=8)
    {
        TB tb = {};
        tb.A[0] = p_ba_r; tb.B[0] = p_bwA; tb.Cc[0] = p_r;    tb.N[0] = C_;  tb.ldc[0] = C_;  tb.epi[0] = EPI_NONE; tb.nch[0] = 96; tb.kc0[0] = 0;
        tb.A[1] = p_ba_g; tb.B[1] = p_bwB; tb.Cc[1] = p_gate; tb.N[1] = C_;  tb.ldc[1] = C_;  tb.epi[1] = EPI_SIG;  tb.nch[1] = 96; tb.kc0[1] = 0;
        tb.A[2] = p_ba_k; tb.B[2] = p_bw1; tb.Cc[2] = p_k;    tb.N[2] = 512; tb.ldc[2] = 512; tb.epi[2] = EPI_NONE; tb.nch[2] = 96; tb.kc0[2] = 0;
        tb.A[3] = p_ba_v; tb.B[3] = p_bw2; tb.Cc[3] = p_v;    tb.N[3] = 512; tb.ldc[3] = 512; tb.epi[3] = EPI_NONE; tb.nch[3] = 96; tb.kc0[3] = 0;
        for (int z = 0; z < SPLITK; z++) {
            tb.A[4 + z] = p_ba_w; tb.B[4 + z] = p_bws2;
            tb.Cc[4 + z] = p_part + (size_t)z * T_ * LDEC_;
            tb.N[4 + z] = LDEC_; tb.ldc[4 + z] = LDEC_; tb.epi[4 + z] = EPI_NONE;
            tb.nch[4 + z] = 96 / SPLITK; tb.kc0[4 + z] = z * (96 / SPLITK);
        }
        hgemm<<<dim3(16, 16, 8), blk, HG_SMEM>>>(tb);
    }

    // 5) t2 = tanh(dec partial sums)
    {
        int n = T_ * LDEC_;
        k_red_tanh<<<(n + EW - 1) / EW, EW>>>(p_part, p_t2, n, n);
    }

    // 6) ew = exp(max(-exp(t2@dec_w2 + tdecay), -5)) AND keff = k*(1-ew)  (FFMA2, K=64)
    {
        Batch bt = {};
        bt.A[0] = p_t2; bt.B[0] = dec_w2; bt.Cc[0] = p_ew; bt.vec[0] = tdecay;
        gemm128<EPI_DECAY><<<dim3(C_ / 128, T_ / 128, 1), blk>>>(bt, LDEC_, C_, C_, C_, LDEC_, nullptr, nullptr);
    }

    // 7) scan: writes gated output as bf16 [hi|lo] into ba_r (reused)
    k_scan<<<H_, 512, SCAN_SMEM>>>(state, ns, p_ba_r);

    // 8) final projection: dout = (out*gate) @ Wo
    {
        TB tb = {};
        tb.A[0] = p_ba_r; tb.B[0] = p_bwC; tb.Cc[0] = dout;
        tb.N[0] = C_; tb.ldc[0] = C_; tb.epi[0] = EPI_NONE; tb.nch[0] = 96; tb.kc0[0] = 0;
        hgemm<<<dim3(16, 16, 1), blk, HG_SMEM>>>(tb);
    }

    // 9) new_state (only if the harness expects both outputs)
    if (out_size >= T_ * C_ + (S_ + 1) * C_) {
        int n = H_ * S_ * S_;
        k_state<<<(n + EW - 1) / EW, EW>>>(dout, x, lenp);
    }
}

// round 17
// speedup vs baseline: 1.6760x; 1.1010x over previous
#include <cuda_runtime.h>
#include <cuda_fp16.h>
#include <math.h>
#include <stdint.h>

#define T_ 2048
#define C_ 2048
#define H_ 32
#define S_ 64
#define HKV_ 8
#define LMAA_ 32
#define LDEC_ 64
#define K2_ (2 * C_)   // activations: [hi|lo] fp16, exact to 2^-22
#define KW_ C_         // weights: single fp16 (hi) — 2-term asymmetric scheme
#define SPLITK 8

// ---------------- f32 scratch ----------------
__device__ float g_sx [T_*C_];
__device__ float g_t1 [T_*5*LMAA_];
__device__ float g_t2 [T_*LDEC_];
__device__ float g_r  [T_*C_];
__device__ float g_k  [T_*HKV_*S_];
__device__ float g_v  [T_*HKV_*S_];
__device__ float g_ew [T_*C_];
__device__ float g_keff[T_*C_];
__device__ float g_gate[T_*C_];
__device__ float g_sfin[H_*S_*S_];
__device__ float g_part[SPLITK * T_ * (5*LMAA_)];   // reused: t1 partials, then dec partials

// ---------------- fp16 buffers ----------------
// Activations: rows [hi(2048) | lo(2048)]. Weights: single fp16 rows (except dec_w1: [hi|lo]).
__device__ __align__(128) __half g_ba_xxx[(size_t)T_ * K2_];
__device__ __align__(128) __half g_ba_r  [(size_t)T_ * K2_];   // xr, later reused for out
__device__ __align__(128) __half g_ba_k  [(size_t)T_ * K2_];
__device__ __align__(128) __half g_ba_v  [(size_t)T_ * K2_];
__device__ __align__(128) __half g_ba_w  [(size_t)T_ * K2_];
__device__ __align__(128) __half g_ba_g  [(size_t)T_ * K2_];
__device__ __align__(128) __half g_bwA[(size_t)2048 * KW_];    // Wq
__device__ __align__(128) __half g_bwB[(size_t)2048 * KW_];    // Wg
__device__ __align__(128) __half g_bwC[(size_t)2048 * KW_];    // Wo
__device__ __align__(128) __half g_bw1[(size_t)512 * KW_];     // Wk
__device__ __align__(128) __half g_bw2[(size_t)512 * KW_];     // Wv
__device__ __align__(128) __half g_bws1[(size_t)256 * KW_];    // maa_w1 (160->256)
__device__ __align__(128) __half g_bws2[(size_t)256 * K2_];    // dec_w1 (64->256), [hi|lo] for 3-term

// ---------------- epilogue ids ----------------
#define EPI_NONE  0
#define EPI_TANH  1
#define EPI_SIG   2
#define EPI_MIX   3
#define EPI_DECAY 4

// ---------------- mma.sync helpers ----------------
__device__ __forceinline__ uint32_t smem_u32(const void* p) {
    uint32_t a;
    asm("{ .reg .u64 t; cvta.to.shared.u64 t, %1; cvt.u32.u64 %0, t; }" : "=r"(a) : "l"(p));
    return a;
}
__device__ __forceinline__ void cp_async16(uint32_t saddr, const void* g) {
    asm volatile("cp.async.cg.shared.global [%0], [%1], 16;" :: "r"(saddr), "l"(g) : "memory");
}
__device__ __forceinline__ void cp_async4(uint32_t saddr, const void* g) {
    asm volatile("cp.async.ca.shared.global [%0], [%1], 4;" :: "r"(saddr), "l"(g) : "memory");
}
__device__ __forceinline__ void ldmatrix_x4(uint32_t* r, uint32_t addr) {
    asm volatile("ldmatrix.sync.aligned.m8n8.x4.shared.b16 {%0,%1,%2,%3}, [%4];"
        : "=r"(r[0]), "=r"(r[1]), "=r"(r[2]), "=r"(r[3]) : "r"(addr));
}
__device__ __forceinline__ void mma16816(float* c, const uint32_t* a, uint32_t b0, uint32_t b1) {
    asm volatile("mma.sync.aligned.m16n8k16.row.col.f32.f16.f16.f32 "
        "{%0,%1,%2,%3}, {%4,%5,%6,%7}, {%8,%9}, {%0,%1,%2,%3};"
        : "+f"(c[0]), "+f"(c[1]), "+f"(c[2]), "+f"(c[3])
        : "r"(a[0]), "r"(a[1]), "r"(a[2]), "r"(a[3]), "r"(b0), "r"(b1));
}

struct TB {
    const __half* A[12];
    const __half* B[12];
    float*        Cc[12];
    int N[12];
    int ldc[12];
    int epi[12];
    int nch[12];   // K chunks (64 wide) in virtual K' space
    int kc0[12];   // start chunk (split-K)
    int ldb[12];   // B row stride (KW_ or K2_)
    int mode[12];  // 0 = 2-term (K'=64ch), 1 = 3-term (K'=96ch, W two-seg)
};

// ---------------- HMMA fp16 GEMM ----------------
// mode 0 (2-term): A chunks = [hi(0..31) | lo(32..63)] read linearly; W chunk = ck & 31 (hi twice).
// mode 1 (3-term): A: ck<32->hi, 32..63->hi(ck-32), 64..95->lo(ck-32); W[hi|lo]: ck<64->ck else ck-64.
// 128x128 CTA tile, 8 warps (2m x 4n), warp 64x32 m16n8k16, BK=64, 3-stage cp.async.
__global__ __launch_bounds__(256, 2)
void hgemm(TB bt)
{
    const int z = blockIdx.z;
    const __half* __restrict__ Ag = bt.A[z];
    const __half* __restrict__ Bg = bt.B[z];
    float* __restrict__ Cg = bt.Cc[z];
    const int N = bt.N[z], ldc = bt.ldc[z], epi = bt.epi[z];
    const int nch = bt.nch[z], kc0 = bt.kc0[z];
    const int ldb = bt.ldb[z], mode = bt.mode[z];
    if (blockIdx.x * 128 >= N) return;

    extern __shared__ char smem[];
    const uint32_t sbase = smem_u32(smem);   // 3 stages x (A 16KB | B 16KB)

    const int tid  = threadIdx.x;
    const int lane = tid & 31;
    const int wid  = tid >> 5;
    const int wm   = wid >> 2;
    const int wn   = wid & 3;
    const int bx = blockIdx.x, by = blockIdx.y;

    float acc[4][4][4];
    #pragma unroll
    for (int i = 0; i < 4; i++)
        #pragma unroll
        for (int j = 0; j < 4; j++)
            #pragma unroll
            for (int k = 0; k < 4; k++) acc[i][j][k] = 0.f;

    const __half* Abase = Ag + (size_t)(by * 128) * K2_;
    const __half* Bbase = Bg + (size_t)(bx * 128) * ldb;

    auto load_stage = [&](int kt, int s) {
        const uint32_t sa = sbase + s * 32768;
        const int ck = kc0 + kt;
        int ak, wk;
        if (mode) { ak = (ck < 32) ? ck : ck - 32; wk = (ck < 64) ? ck : ck - 64; }
        else      { ak = ck;                        wk = (ck < 32) ? ck : ck - 32; }
        const __half* Agk = Abase + (size_t)ak * 64;
        const __half* Bgk = Bbase + (size_t)wk * 64;
        #pragma unroll
        for (int q = 0; q < 4; q++) {
            const int c = q * 256 + tid;
            const int row = c >> 3, j = c & 7;
            uint32_t off = (uint32_t)(row * 128 + j * 16);
            off ^= (off >> 3) & 0x70;
            cp_async16(sa + off,         Agk + (size_t)row * K2_ + j * 8);
            cp_async16(sa + 16384 + off, Bgk + (size_t)row * ldb + j * 8);
        }
        asm volatile("cp.async.commit_group;" ::: "memory");
    };

    const int a_roff = (wm * 64 + (lane & 15)) * 128 + (lane >> 4) * 16;
    const int b_roff = (wn * 32 + (lane & 7) + ((lane >> 4) << 3)) * 128 + ((lane >> 3) & 1) * 16;

    auto compute = [&](int s) {
        const uint32_t sa = sbase + s * 32768;
        const uint32_t sbb = sa + 16384;
        #pragma unroll
        for (int ks = 0; ks < 4; ks++) {
            uint32_t bf2[2][4];
            #pragma unroll
            for (int nt2 = 0; nt2 < 2; nt2++) {
                uint32_t off = (uint32_t)(b_roff + nt2 * 16 * 128 + ks * 32);
                off ^= (off >> 3) & 0x70;
                ldmatrix_x4(bf2[nt2], sbb + off);
            }
            uint32_t af[4][4];
            #pragma unroll
            for (int mt = 0; mt < 4; mt++) {
                uint32_t off = (uint32_t)(a_roff + mt * 16 * 128 + ks * 32);
                off ^= (off >> 3) & 0x70;
                ldmatrix_x4(af[mt], sa + off);
            }
            #pragma unroll
            for (int mt = 0; mt < 4; mt++)
                #pragma unroll
                for (int nt = 0; nt < 4; nt++)
                    mma16816(acc[mt][nt], af[mt],
                             bf2[nt >> 1][(nt & 1) * 2], bf2[nt >> 1][(nt & 1) * 2 + 1]);
        }
    };

    load_stage(0, 0);
    load_stage(1, 1);

    for (int kt = 0; kt < nch; kt++) {
        asm volatile("cp.async.wait_group 1;" ::: "memory");
        __syncthreads();
        if (kt + 2 < nch) load_stage(kt + 2, (kt + 2) % 3);
        else asm volatile("cp.async.commit_group;" ::: "memory");
        compute(kt % 3);
    }

    #pragma unroll
    for (int mt = 0; mt < 4; mt++) {
        #pragma unroll
        for (int hrow = 0; hrow < 2; hrow++) {
            const int row = by * 128 + wm * 64 + mt * 16 + hrow * 8 + (lane >> 2);
            float* crow = Cg + (size_t)row * ldc;
            #pragma unroll
            for (int nt = 0; nt < 4; nt++) {
                const int col = bx * 128 + wn * 32 + nt * 8 + (lane & 3) * 2;
                if (col >= N) continue;
                float v0 = acc[mt][nt][hrow * 2 + 0];
                float v1 = acc[mt][nt][hrow * 2 + 1];
                if (epi == EPI_TANH) { v0 = tanhf(v0); v1 = tanhf(v1); }
                else if (epi == EPI_SIG) { v0 = 1.f/(1.f+expf(-v0)); v1 = 1.f/(1.f+expf(-v1)); }
                *(float2*)&crow[col] = make_float2(v0, v1);
            }
        }
    }
}

// ---------------- split-K reducer + tanh (8 partials) ----------------
__global__ void k_red_tanh(const float* __restrict__ part, float* __restrict__ out,
                           int n, int stride)
{
    int i = blockIdx.x * blockDim.x + threadIdx.x;
    if (i >= n) return;
    float s = 0.f;
    #pragma unroll
    for (int z = 0; z < SPLITK; z++) s += part[(size_t)z * stride + i];
    out[i] = tanhf(s);
}

// ---------------- batched weight conversion (ALL weights, one launch) ----------------
// src[2048 x N] f32 -> dst[Npad x ld] fp16, transposed. twoseg: also write lo at +C_.
struct CB {
    const float* src[7];
    __half*      dst[7];
    int          N[7];
    int          xt[7];
    int          ld[7];
    int          twoseg[7];
};

__global__ void k_conv_all(CB cb)
{
    __shared__ float tile[32][33];
    int bx = blockIdx.x;
    int w = 0;
    while (bx >= cb.xt[w]) { bx -= cb.xt[w]; w++; }
    const float* __restrict__ src = cb.src[w];
    __half* __restrict__ dst = cb.dst[w];
    const int N = cb.N[w];
    const int ld = cb.ld[w];
    const int twoseg = cb.twoseg[w];

    const int n0 = bx * 32;
    const int k0 = blockIdx.y * 32;
    const int tx = threadIdx.x, ty = threadIdx.y;  // (32, 8)
    #pragma unroll
    for (int yy = 0; yy < 32; yy += 8) {
        int n = n0 + tx, k = k0 + ty + yy;
        tile[ty + yy][tx] = (n < N) ? src[(size_t)k * N + n] : 0.f;
    }
    __syncthreads();
    #pragma unroll
    for (int yy = 0; yy < 32; yy += 8) {
        int n = n0 + ty + yy;
        int k = k0 + tx;
        float a = tile[tx][ty + yy];
        __half hi = __float2half(a);
        size_t base = (size_t)n * ld;
        dst[base + k] = hi;
        if (twoseg) dst[base + C_ + k] = __float2half(a - __half2float(hi));
    }
}

// ---------------- FFMA2 GEMM (MIX K=32 -> fp16 [hi|lo] out, DECAY K=64 -> ew + keff) ----
struct Batch {
    const float* A[8];
    const float* B[8];
    void*        Cc[8];
    const float* vec[8];
};

template<int EPI>
__global__ __launch_bounds__(256, 2)
void gemm128(Batch bt, int lda, int ldb, int ldc, int N, int K,
             const float* __restrict__ aux1, const float* __restrict__ aux2)
{
    __shared__ float2 As[2][16][128];
    __shared__ float  Bs[2][16][128];

    const int z = blockIdx.z;
    const float* __restrict__ A   = bt.A[z];
    const float* __restrict__ B   = bt.B[z];
    const float* __restrict__ vec = bt.vec[z];

    const int tid = threadIdx.x;
    const int bx = blockIdx.x, by = blockIdx.y;
    const int arow = tid >> 1,  acol = (tid & 1) * 8;
    const int brow = tid >> 4,  bcol = (tid & 15) * 8;
    const int tx = tid & 15,    ty = tid >> 4;

    unsigned long long acc[8][4];
    #pragma unroll
    for (int i = 0; i < 8; i++)
        #pragma unroll
        for (int j = 0; j < 4; j++) acc[i][j] = 0ULL;

    const float* Ap = A + (size_t)(by * 128 + arow) * lda + acol;
    const int gcolb = bx * 128 + bcol;

    float4 a0, a1, b0, b1;
    auto loadAB = [&](int k0) {
        a0 = *(const float4*)(Ap + k0);
        a1 = *(const float4*)(Ap + k0 + 4);
        const float* bp = B + (size_t)(k0 + brow) * ldb + gcolb;
        b0 = *(const float4*)bp;
        b1 = *(const float4*)(bp + 4);
    };
    auto storeAB = [&](int buf) {
        As[buf][acol + 0][arow] = make_float2(a0.x, a0.x);
        As[buf][acol + 1][arow] = make_float2(a0.y, a0.y);
        As[buf][acol + 2][arow] = make_float2(a0.z, a0.z);
        As[buf][acol + 3][arow] = make_float2(a0.w, a0.w);
        As[buf][acol + 4][arow] = make_float2(a1.x, a1.x);
        As[buf][acol + 5][arow] = make_float2(a1.y, a1.y);
        As[buf][acol + 6][arow] = make_float2(a1.z, a1.z);
        As[buf][acol + 7][arow] = make_float2(a1.w, a1.w);
        *(float4*)&Bs[buf][brow][bcol]     = b0;
        *(float4*)&Bs[buf][brow][bcol + 4] = b1;
    };

    loadAB(0);
    storeAB(0);
    __syncthreads();

    const int nt = K >> 4;
    for (int kt = 0; kt < nt; kt++) {
        const int cur = kt & 1;
        if (kt + 1 < nt) loadAB((kt + 1) << 4);

        #pragma unroll
        for (int kk = 0; kk < 16; kk++) {
            unsigned long long a2[8], b2[4];
            const ulonglong2* ap = (const ulonglong2*)&As[cur][kk][ty * 8];
            ulonglong2 w;
            w = ap[0]; a2[0] = w.x; a2[1] = w.y;
            w = ap[1]; a2[2] = w.x; a2[3] = w.y;
            w = ap[2]; a2[4] = w.x; a2[5] = w.y;
            w = ap[3]; a2[6] = w.x; a2[7] = w.y;
            const ulonglong2* bp2 = (const ulonglong2*)&Bs[cur][kk][tx * 8];
            w = bp2[0]; b2[0] = w.x; b2[1] = w.y;
            w = bp2[1]; b2[2] = w.x; b2[3] = w.y;
            #pragma unroll
            for (int i = 0; i < 8; i++)
                #pragma unroll
                for (int j = 0; j < 4; j++)
                    asm("fma.rn.f32x2 %0, %1, %2, %0;"
                        : "+l"(acc[i][j]) : "l"(a2[i]), "l"(b2[j]));
        }

        if (kt + 1 < nt) storeAB(cur ^ 1);
        __syncthreads();
    }

    #pragma unroll
    for (int i = 0; i < 8; i++) {
        const int row = by * 128 + ty * 8 + i;
        #pragma unroll
        for (int j = 0; j < 4; j++) {
            const int col = bx * 128 + tx * 8 + 2 * j;
            float v0 = __uint_as_float((unsigned)(acc[i][j] & 0xffffffffULL));
            float v1 = __uint_as_float((unsigned)(acc[i][j] >> 32));
            if (EPI == EPI_MIX) {
                size_t idx = (size_t)row * C_ + col;
                v0 = aux1[idx]     + aux2[idx]     * (vec[col]     + v0);
                v1 = aux1[idx + 1] + aux2[idx + 1] * (vec[col + 1] + v1);
                __half h0 = __float2half(v0);
                __half h1 = __float2half(v1);
                __half l0 = __float2half(v0 - __half2float(h0));
                __half l1 = __float2half(v1 - __half2float(h1));
                __half2 hh; hh.x = h0; hh.y = h1;
                __half2 ll; ll.x = l0; ll.y = l1;
                __half* bout = (__half*)bt.Cc[z];
                size_t base = (size_t)row * K2_;
                *(__half2*)&bout[base + col]      = hh;
                *(__half2*)&bout[base + C_ + col] = ll;
            } else {  // EPI_DECAY: write ew AND keff = k*(1-ew)
                float* crow = (float*)bt.Cc[z] + (size_t)row * ldc;
                float lw0 = fmaxf(-expf(v0 + vec[col]), -5.0f);
                float lw1 = fmaxf(-expf(v1 + vec[col + 1]), -5.0f);
                float e0 = expf(lw0), e1 = expf(lw1);
                *(float2*)&crow[col] = make_float2(e0, e1);
                int hh2 = col >> 6, ss = col & 63;
                float2 kv = *(const float2*)&g_k[(size_t)row * 512 + (hh2 >> 2) * 64 + ss];
                *(float2*)&g_keff[(size_t)row * C_ + col] =
                    make_float2(kv.x * (1.f - e0), kv.y * (1.f - e1));
            }
        }
    }
}

// ---------------- token shift: writes sx (f32) + xxx (fp16 [hi|lo]) ----------------
__global__ void k_shift(const float* __restrict__ x, const float* __restrict__ state,
                        const unsigned char* __restrict__ ns,
                        const float* __restrict__ maa_x)
{
    int idx = blockIdx.x * blockDim.x + threadIdx.x;
    if (idx >= T_ * C_) return;
    int t = idx >> 11;
    int c = idx & 2047;
    float prev = (t == 0) ? state[c] : x[idx - C_];
    if (ns[t]) prev = 0.f;
    float s = prev - x[idx];
    g_sx[idx] = s;
    float v = x[idx] + s * maa_x[c];
    __half hi = __float2half(v);
    size_t base = (size_t)t * K2_;
    g_ba_xxx[base + c]      = hi;
    g_ba_xxx[base + C_ + c] = __float2half(v - __half2float(hi));
}

// ---------------- RWKV scan v3: cp.async ring, 2 barriers per 8 steps ----------------
#define SCAN_SLOT 320                          // floats per slot: r|keff|ew|v|gate
#define SCAN_SMEM (32*SCAN_SLOT*4 + 8*512*4 + T_)

__global__ __launch_bounds__(512)
void k_scan(const float* __restrict__ state, const unsigned char* __restrict__ ns,
            __half* __restrict__ out_split)
{
    extern __shared__ char sm[];
    float* ring = (float*)sm;                                   // [32][320]
    float* pbuf = (float*)(sm + 32 * SCAN_SLOT * 4);            // [8][512]
    unsigned char* nsh = (unsigned char*)(sm + 32 * SCAN_SLOT * 4 + 8 * 512 * 4);

    const int h = blockIdx.x;
    const int tid = threadIdx.x;
    const int vcol = tid >> 3;
    const int kg = tid & 7;

    unsigned long long s2[4];
    #pragma unroll
    for (int j2 = 0; j2 < 4; j2++) {
        float slo = state[C_ + h * 4096 + (kg * 8 + 2 * j2) * 64 + vcol];
        float shi = state[C_ + h * 4096 + (kg * 8 + 2 * j2 + 1) * 64 + vcol];
        asm("mov.b64 %0, {%1, %2};" : "=l"(s2[j2]) : "f"(slo), "f"(shi));
    }

    for (int i = tid; i < T_; i += 512) nsh[i] = ns[i];

    const int a  = tid >> 6;
    const int li = tid & 63;
    const bool loader = (a < 5);
    const float* src = nullptr;
    int stride = C_;
    if (a == 0)      src = g_r    + (size_t)h * 64 + li;
    else if (a == 1) src = g_keff + (size_t)h * 64 + li;
    else if (a == 2) src = g_ew   + (size_t)h * 64 + li;
    else if (a == 3) { src = g_v + (size_t)(h >> 2) * 64 + li; stride = 512; }
    else if (a == 4) src = g_gate + (size_t)h * 64 + li;

    const uint32_t sring = smem_u32(ring);
    const uint32_t dbase = (uint32_t)(a * 64 + li) * 4;

    auto issue8 = [&](int tbase) {
        if (loader) {
            #pragma unroll
            for (int p = 0; p < 8; p++) {
                int t = tbase + p;
                cp_async4(sring + (uint32_t)((t & 31) * SCAN_SLOT) * 4 + dbase,
                          src + (size_t)t * stride);
            }
        }
        asm volatile("cp.async.commit_group;" ::: "memory");
    };

    issue8(0);
    issue8(8);

    for (int S = 0; S < T_ / 8; S++) {
        const int t0 = S * 8;
        if (t0 + 16 < T_) issue8(t0 + 16);
        else asm volatile("cp.async.commit_group;" ::: "memory");
        asm volatile("cp.async.wait_group 2;" ::: "memory");
        __syncthreads();

        #pragma unroll
        for (int p = 0; p < 8; p++) {
            const int t = t0 + p;
            const float* Sl = ring + (t & 31) * SCAN_SLOT;

            float vv = Sl[3 * 64 + vcol];
            unsigned long long vv2;
            asm("mov.b64 %0, {%1, %1};" : "=l"(vv2) : "f"(vv));

            const bool reset = (nsh[t] != 0);

            const ulonglong2* rp = (const ulonglong2*)&Sl[0 * 64 + kg * 8];
            const ulonglong2* kp = (const ulonglong2*)&Sl[1 * 64 + kg * 8];
            const ulonglong2* wp = (const ulonglong2*)&Sl[2 * 64 + kg * 8];
            ulonglong2 rA = rp[0], rB = rp[1];
            ulonglong2 kA = kp[0], kB = kp[1];
            ulonglong2 wA = wp[0], wB = wp[1];
            unsigned long long r2[4] = { rA.x, rA.y, rB.x, rB.y };
            unsigned long long k2[4] = { kA.x, kA.y, kB.x, kB.y };
            unsigned long long w2[4] = { wA.x, wA.y, wB.x, wB.y };

            unsigned long long ps2 = 0ULL;
            #pragma unroll
            for (int j2 = 0; j2 < 4; j2++) {
                if (reset) s2[j2] = 0ULL;
                unsigned long long kv2;
                asm("mul.rn.f32x2 %0, %1, %2;"     : "=l"(kv2)    : "l"(k2[j2]), "l"(vv2));
                asm("fma.rn.f32x2 %0, %1, %2, %3;" : "=l"(s2[j2]) : "l"(s2[j2]), "l"(w2[j2]), "l"(kv2));
                asm("fma.rn.f32x2 %0, %1, %2, %0;" : "+l"(ps2)    : "l"(r2[j2]), "l"(s2[j2]));
            }

            float plo = __uint_as_float((unsigned)(ps2 & 0xffffffffULL));
            float phi = __uint_as_float((unsigned)(ps2 >> 32));
            pbuf[p * 512 + tid] = plo + phi;
        }
        __syncthreads();

        {
            const int st = tid >> 6;
            const int vc = tid & 63;
            const float4* p4 = (const float4*)&pbuf[st * 512 + vc * 8];
            float4 x0 = p4[0], x1 = p4[1];
            float o = ((x0.x + x0.y) + (x0.z + x0.w)) + ((x1.x + x1.y) + (x1.z + x1.w));
            const int t = t0 + st;
            o *= ring[(t & 31) * SCAN_SLOT + 4 * 64 + vc];
            __half hi = __float2half(o);
            size_t base = (size_t)t * K2_;
            int c = h * 64 + vc;
            out_split[base + c]      = hi;
            out_split[base + C_ + c] = __float2half(o - __half2float(hi));
        }
    }

    #pragma unroll
    for (int j2 = 0; j2 < 4; j2++) {
        float slo = __uint_as_float((unsigned)(s2[j2] & 0xffffffffULL));
        float shi = __uint_as_float((unsigned)(s2[j2] >> 32));
        g_sfin[h * 4096 + (kg * 8 + 2 * j2) * 64 + vcol]     = slo;
        g_sfin[h * 4096 + (kg * 8 + 2 * j2 + 1) * 64 + vcol] = shi;
    }
}

// ---------------- new_state writer ----------------
__global__ void k_state(float* __restrict__ dout, const float* __restrict__ x,
                        const int* __restrict__ lenp)
{
    int idx = blockIdx.x * blockDim.x + threadIdx.x;
    int L = lenp ? lenp[0] : T_;
    if (idx < C_)
        dout[(size_t)T_ * C_ + idx] = x[(size_t)(L - 1) * C_ + idx];
    if (idx < H_ * S_ * S_)
        dout[(size_t)T_ * C_ + C_ + idx] = g_sfin[idx];
}

// ---------------- host-side orchestration ----------------
template <typename Sym>
static void* devaddr_v(Sym& sym) {
    void* p = nullptr;
    cudaGetSymbolAddress(&p, sym);
    return p;
}

#define HG_SMEM (3 * 32768)

extern "C" void kernel_launch(void* const* d_in, const int* in_sizes, int n_in,
                              void* d_out, int out_size)
{
    int i = 0;
    const float* x       = (const float*)d_in[i++];
    const float* state   = (const float*)d_in[i++];
    const unsigned char* ns = (const unsigned char*)d_in[i++];
    const int* lenp = nullptr;
    if (n_in >= 20) { lenp = (const int*)d_in[i++]; }
    const float* maa_x = (const float*)d_in[i++];
    const float* maa_r = (const float*)d_in[i++];
    const float* maa_k = (const float*)d_in[i++];
    const float* maa_v = (const float*)d_in[i++];
    const float* maa_w = (const float*)d_in[i++];
    const float* maa_g = (const float*)d_in[i++];
    const float* maa_w1 = (const float*)d_in[i++];  // [C, 160]
    const float* maa_w2 = (const float*)d_in[i++];  // [5, 32, C]
    const float* tdecay = (const float*)d_in[i++];  // [C]
    const float* dec_w1 = (const float*)d_in[i++];  // [C, 64]
    const float* dec_w2 = (const float*)d_in[i++];  // [64, C]
    const float* Wq = (const float*)d_in[i++];      // [C, C]
    const float* Wk = (const float*)d_in[i++];      // [C, 512]
    const float* Wv = (const float*)d_in[i++];      // [C, 512]
    const float* Wg = (const float*)d_in[i++];      // [C, C]
    const float* Wo = (const float*)d_in[i++];      // [C, C]
    float* dout = (float*)d_out;

    float* p_sx   = (float*)devaddr_v(g_sx);
    float* p_t1   = (float*)devaddr_v(g_t1);
    float* p_t2   = (float*)devaddr_v(g_t2);
    float* p_r    = (float*)devaddr_v(g_r);
    float* p_k    = (float*)devaddr_v(g_k);
    float* p_v    = (float*)devaddr_v(g_v);
    float* p_ew   = (float*)devaddr_v(g_ew);
    float* p_gate = (float*)devaddr_v(g_gate);
    float* p_part = (float*)devaddr_v(g_part);
    __half* p_ba_xxx = (__half*)devaddr_v(g_ba_xxx);
    __half* p_ba_r   = (__half*)devaddr_v(g_ba_r);
    __half* p_ba_k   = (__half*)devaddr_v(g_ba_k);
    __half* p_ba_v   = (__half*)devaddr_v(g_ba_v);
    __half* p_ba_w   = (__half*)devaddr_v(g_ba_w);
    __half* p_ba_g   = (__half*)devaddr_v(g_ba_g);
    __half* p_bwA  = (__half*)devaddr_v(g_bwA);
    __half* p_bwB  = (__half*)devaddr_v(g_bwB);
    __half* p_bwC  = (__half*)devaddr_v(g_bwC);
    __half* p_bw1  = (__half*)devaddr_v(g_bw1);
    __half* p_bw2  = (__half*)devaddr_v(g_bw2);
    __half* p_bws1 = (__half*)devaddr_v(g_bws1);
    __half* p_bws2 = (__half*)devaddr_v(g_bws2);

    cudaFuncSetAttribute(hgemm, cudaFuncAttributeMaxDynamicSharedMemorySize, HG_SMEM);
    cudaFuncSetAttribute(k_scan, cudaFuncAttributeMaxDynamicSharedMemorySize, SCAN_SMEM);

    const int EW = 256;
    const int GE = (T_ * C_ + EW - 1) / EW;
    dim3 blk(256);
    dim3 cw(32, 8);

    // 0) ALL weight conversions in one launch
    {
        CB cb = {};
        cb.src[0] = Wq;     cb.dst[0] = p_bwA;  cb.N[0] = C_;        cb.xt[0] = 64; cb.ld[0] = KW_; cb.twoseg[0] = 0;
        cb.src[1] = Wg;     cb.dst[1] = p_bwB;  cb.N[1] = C_;        cb.xt[1] = 64; cb.ld[1] = KW_; cb.twoseg[1] = 0;
        cb.src[2] = Wo;     cb.dst[2] = p_bwC;  cb.N[2] = C_;        cb.xt[2] = 64; cb.ld[2] = KW_; cb.twoseg[2] = 0;
        cb.src[3] = Wk;     cb.dst[3] = p_bw1;  cb.N[3] = 512;       cb.xt[3] = 16; cb.ld[3] = KW_; cb.twoseg[3] = 0;
        cb.src[4] = Wv;     cb.dst[4] = p_bw2;  cb.N[4] = 512;       cb.xt[4] = 16; cb.ld[4] = KW_; cb.twoseg[4] = 0;
        cb.src[5] = maa_w1; cb.dst[5] = p_bws1; cb.N[5] = 5 * LMAA_; cb.xt[5] = 8;  cb.ld[5] = KW_; cb.twoseg[5] = 0;
        cb.src[6] = dec_w1; cb.dst[6] = p_bws2; cb.N[6] = LDEC_;     cb.xt[6] = 8;  cb.ld[6] = K2_; cb.twoseg[6] = 1;
        k_conv_all<<<dim3(240, 64), cw>>>(cb);
    }

    // 1) token shift -> sx (f32) + ba_xxx (fp16 [hi|lo])
    k_shift<<<GE, EW>>>(x, state, ns, maa_x);

    // 2) t1 = tanh(xxx @ maa_w1) [T,160]: 2-term, split-K 8 + reduce
    {
        TB tb = {};
        for (int z = 0; z < SPLITK; z++) {
            tb.A[z] = p_ba_xxx; tb.B[z] = p_bws1;
            tb.Cc[z] = p_part + (size_t)z * T_ * (5 * LMAA_);
            tb.N[z] = 5 * LMAA_; tb.ldc[z] = 5 * LMAA_; tb.epi[z] = EPI_NONE;
            tb.nch[z] = 64 / SPLITK; tb.kc0[z] = z * (64 / SPLITK);
            tb.ldb[z] = KW_; tb.mode[z] = 0;
        }
        hgemm<<<dim3(2, 16, SPLITK), blk, HG_SMEM>>>(tb);
        int n = T_ * 5 * LMAA_;
        k_red_tanh<<<(n + EW - 1) / EW, EW>>>(p_part, p_t1, n, n);
    }

    // 3) MIX (FFMA2, K=32): writes 5 fp16 [hi|lo] activation buffers
    {
        Batch bt = {};
        const float* vecs[5] = { maa_r, maa_k, maa_v, maa_w, maa_g };
        void* outs[5] = { p_ba_r, p_ba_k, p_ba_v, p_ba_w, p_ba_g };
        for (int z = 0; z < 5; z++) {
            bt.A[z]  = p_t1 + z * LMAA_;
            bt.B[z]  = maa_w2 + (size_t)z * LMAA_ * C_;
            bt.Cc[z] = outs[z];
            bt.vec[z] = vecs[z];
        }
        gemm128<EPI_MIX><<<dim3(C_ / 128, T_ / 128, 5), blk>>>(bt, 5 * LMAA_, C_, C_, C_, LMAA_, x, p_sx);
    }

    // 4) r + gate + k + v (2-term) + dec-splitK8 (3-term) in ONE launch (z=12)
    {
        TB tb = {};
        tb.A[0] = p_ba_r; tb.B[0] = p_bwA; tb.Cc[0] = p_r;    tb.N[0] = C_;  tb.ldc[0] = C_;  tb.epi[0] = EPI_NONE; tb.nch[0] = 64; tb.kc0[0] = 0; tb.ldb[0] = KW_; tb.mode[0] = 0;
        tb.A[1] = p_ba_g; tb.B[1] = p_bwB; tb.Cc[1] = p_gate; tb.N[1] = C_;  tb.ldc[1] = C_;  tb.epi[1] = EPI_SIG;  tb.nch[1] = 64; tb.kc0[1] = 0; tb.ldb[1] = KW_; tb.mode[1] = 0;
        tb.A[2] = p_ba_k; tb.B[2] = p_bw1; tb.Cc[2] = p_k;    tb.N[2] = 512; tb.ldc[2] = 512; tb.epi[2] = EPI_NONE; tb.nch[2] = 64; tb.kc0[2] = 0; tb.ldb[2] = KW_; tb.mode[2] = 0;
        tb.A[3] = p_ba_v; tb.B[3] = p_bw2; tb.Cc[3] = p_v;    tb.N[3] = 512; tb.ldc[3] = 512; tb.epi[3] = EPI_NONE; tb.nch[3] = 64; tb.kc0[3] = 0; tb.ldb[3] = KW_; tb.mode[3] = 0;
        for (int z = 0; z < SPLITK; z++) {
            tb.A[4 + z] = p_ba_w; tb.B[4 + z] = p_bws2;
            tb.Cc[4 + z] = p_part + (size_t)z * T_ * LDEC_;
            tb.N[4 + z] = LDEC_; tb.ldc[4 + z] = LDEC_; tb.epi[4 + z] = EPI_NONE;
            tb.nch[4 + z] = 96 / SPLITK; tb.kc0[4 + z] = z * (96 / SPLITK);
            tb.ldb[4 + z] = K2_; tb.mode[4 + z] = 1;
        }
        hgemm<<<dim3(16, 16, 12), blk, HG_SMEM>>>(tb);
    }

    // 5) t2 = tanh(dec partial sums)
    {
        int n = T_ * LDEC_;
        k_red_tanh<<<(n + EW - 1) / EW, EW>>>(p_part, p_t2, n, n);
    }

    // 6) ew = exp(max(-exp(t2@dec_w2 + tdecay), -5)) AND keff = k*(1-ew)  (FFMA2, K=64)
    {
        Batch bt = {};
        bt.A[0] = p_t2; bt.B[0] = dec_w2; bt.Cc[0] = p_ew; bt.vec[0] = tdecay;
        gemm128<EPI_DECAY><<<dim3(C_ / 128, T_ / 128, 1), blk>>>(bt, LDEC_, C_, C_, C_, LDEC_, nullptr, nullptr);
    }

    // 7) scan: writes gated output as fp16 [hi|lo] into ba_r (reused)
    k_scan<<<H_, 512, SCAN_SMEM>>>(state, ns, p_ba_r);

    // 8) final projection: dout = (out*gate) @ Wo  (2-term)
    {
        TB tb = {};
        tb.A[0] = p_ba_r; tb.B[0] = p_bwC; tb.Cc[0] = dout;
        tb.N[0] = C_; tb.ldc[0] = C_; tb.epi[0] = EPI_NONE;
        tb.nch[0] = 64; tb.kc0[0] = 0; tb.ldb[0] = KW_; tb.mode[0] = 0;
        hgemm<<<dim3(16, 16, 1), blk, HG_SMEM>>>(tb);
    }

    // 9) new_state (only if the harness expects both outputs)
    if (out_size >= T_ * C_ + (S_ + 1) * C_) {
        int n = H_ * S_ * S_;
        k_state<<<(n + EW - 1) / EW, EW>>>(dout, x, lenp);
    }
}